// round 2
// baseline (speedup 1.0000x reference)
#include <cuda_runtime.h>

#define BB 8
#define NN 1024
#define DIN 512
#define HH 8
#define DHd 64
#define INNER 512
#define DOUT 512
#define NROWS (BB*NN)            // 8192
#define QKV_COLS 1536
#define SCALE 0.125f
#define LOG2E 1.4426950408889634f

// ---- scratch (device globals; no runtime allocation) ----
__device__ float g_qkv[(size_t)NROWS * QKV_COLS];          // q|k|v per row, 48MB
__device__ float g_bias_t[(size_t)BB * HH * NN * NN];      // bias transposed+masked, 256MB
__device__ float g_att[(size_t)NROWS * INNER];             // attention output (b,n,(h d)), 16MB
__device__ unsigned char g_maskb[BB * NN];                 // expanded mask flags (1=keep)

// ---- helpers ----
__device__ __forceinline__ float to_tf32(float x) {
    unsigned u;
    asm("cvt.rna.tf32.f32 %0, %1;" : "=r"(u) : "f"(x));
    return __uint_as_float(u);
}
__device__ __forceinline__ float ex2(float x) {
    float y;
    asm("ex2.approx.ftz.f32 %0, %1;" : "=f"(y) : "f"(x));
    return y;
}
__device__ __forceinline__ void mma8(float& c0, float& c1, float& c2, float& c3,
                                     unsigned a0, unsigned a1, unsigned a2, unsigned a3,
                                     unsigned b0, unsigned b1) {
    asm volatile(
        "mma.sync.aligned.m16n8k8.row.col.f32.tf32.tf32.f32 "
        "{%0,%1,%2,%3},{%4,%5,%6,%7},{%8,%9},{%0,%1,%2,%3};\n"
        : "+f"(c0), "+f"(c1), "+f"(c2), "+f"(c3)
        : "r"(a0), "r"(a1), "r"(a2), "r"(a3), "r"(b0), "r"(b1));
}

// =====================================================================
// Kernel 0: mask dtype detection + expansion.
// The harness may deliver the bool mask as uint8, int32, or float32. We only
// know the element count (8192). Reading the FIRST 8192 bytes is safe in all
// cases. Classify layout from byte patterns, then expand to g_maskb.
//   int32 0/1 little-endian -> bytes at (idx%4 != 0) are all zero
//   float32 0.0/1.0         -> every aligned word is 0x00000000 or 0x3F800000
//   uint8                   -> anything else
// One CTA, 256 threads.
// =====================================================================
__global__ __launch_bounds__(256) void k_mask_expand(const unsigned char* __restrict__ m) {
    __shared__ int s_notI32, s_notF32;
    if (threadIdx.x == 0) { s_notI32 = 0; s_notF32 = 0; }
    __syncthreads();
    const unsigned* mw = (const unsigned*)m;
    int notI = 0, notF = 0;
    for (int i = threadIdx.x; i < BB * NN / 4; i += 256) {       // 2048 words
        unsigned w = mw[i];
        if (w & 0xFFFFFF00u) notI = 1;                           // bytes 1..3 nonzero
        if (w != 0u && w != 0x3F800000u) notF = 1;
    }
    if (notI) atomicOr(&s_notI32, 1);
    if (notF) atomicOr(&s_notF32, 1);
    __syncthreads();
    const int notI32 = s_notI32, notF32 = s_notF32;
    for (int i = threadIdx.x; i < BB * NN; i += 256) {
        unsigned char v;
        if (!notF32) {                         // float32 0.0/1.0
            v = (((const unsigned*)m)[i] != 0u) ? 1 : 0;
        } else if (!notI32) {                  // int32 0/1
            v = (((const int*)m)[i] != 0) ? 1 : 0;
        } else {                               // raw uint8 bool
            v = (m[i] != 0) ? 1 : 0;
        }
        g_maskb[i] = v;
    }
}

// =====================================================================
// Kernel 1: bias transpose + key mask fuse.
// bias_t[b,h,i,j] = mask[b,j] ? sim_bias[b,i,j,h] : -1e30
// one CTA per (b,i); smem transpose of [1024 j][8 h]
// =====================================================================
__global__ __launch_bounds__(256) void k_bias_transpose(const float* __restrict__ bias) {
    __shared__ float s[NN * 9];
    __shared__ unsigned char ms[NN];
    const int bi = blockIdx.x;
    const int b = bi >> 10;
    const int i = bi & (NN - 1);
    const float* src = bias + (size_t)bi * (NN * HH);

    // load 8192 floats as 2048 float4 (coalesced)
    #pragma unroll
    for (int sIt = 0; sIt < 8; sIt++) {
        int idx = threadIdx.x + sIt * 256;          // float4 index
        float4 v = *(const float4*)(src + idx * 4);
        int j = idx >> 1;
        int h = (idx & 1) * 4;
        s[j * 9 + h + 0] = v.x;
        s[j * 9 + h + 1] = v.y;
        s[j * 9 + h + 2] = v.z;
        s[j * 9 + h + 3] = v.w;
    }
    for (int j = threadIdx.x; j < NN; j += 256) ms[j] = g_maskb[b * NN + j];
    __syncthreads();

    #pragma unroll
    for (int h = 0; h < HH; h++) {
        float* dst = g_bias_t + (((size_t)(b * HH + h)) * NN + i) * NN;
        int j4 = threadIdx.x;                        // exactly NN/4 == 256 threads
        int j = j4 * 4;
        float4 o;
        o.x = ms[j + 0] ? s[(j + 0) * 9 + h] : -1e30f;
        o.y = ms[j + 1] ? s[(j + 1) * 9 + h] : -1e30f;
        o.z = ms[j + 2] ? s[(j + 2) * 9 + h] : -1e30f;
        o.w = ms[j + 3] ? s[(j + 3) * 9 + h] : -1e30f;
        *(float4*)(dst + j) = o;
    }
}

// =====================================================================
// Kernel 2/4: 64x64-tile GEMM, K=512, 3xTF32 (hi/lo split) for fp32-class accuracy.
// mode 0: C(g_qkv)[8192,1536] = x[8192,512] @ [Wq | Wkv]
// mode 1: C(d_out)[8192,512]  = g_att[8192,512] @ Wout + bout
// 128 threads, 4 warps; warp w owns rows [16w,16w+16) x 64 cols.
// =====================================================================
#define GA_S 36
#define GB_S 68
__global__ __launch_bounds__(128) void k_gemm3x(int mode, const float* __restrict__ Ain,
                                                const float* __restrict__ B0,
                                                const float* __restrict__ B1,
                                                const float* __restrict__ bias,
                                                float* __restrict__ Cout) {
    __shared__ float Ah[64 * GA_S], Al[64 * GA_S], Bh[32 * GB_S], Bl[32 * GB_S];
    const int tid = threadIdx.x, lane = tid & 31, warp = tid >> 5;
    const int g = lane >> 2, t = lane & 3;
    const int cb = blockIdx.x * 64;
    const int rb = blockIdx.y * 64;

    const float* A = (mode == 0) ? Ain : g_att;
    float* C = (mode == 0) ? g_qkv : Cout;
    const int ldc = (mode == 0) ? QKV_COLS : DOUT;

    const float* Bp;
    int ldb, c0;
    if (B1 != nullptr && cb >= 512) { Bp = B1; ldb = 1024; c0 = cb - 512; }
    else { Bp = B0; ldb = 512; c0 = cb; }

    float acc[8][4];
    #pragma unroll
    for (int i = 0; i < 8; i++)
        #pragma unroll
        for (int j = 0; j < 4; j++) acc[i][j] = 0.f;

    float4 ra[4], rbv[4];
    #pragma unroll
    for (int sIt = 0; sIt < 4; sIt++) {
        int idx = tid + sIt * 128;
        int r = idx >> 3, cc = (idx & 7) * 4;                 // A tile 64x32
        ra[sIt] = *(const float4*)(A + (size_t)(rb + r) * 512 + cc);
        int rB = idx >> 4, cB = (idx & 15) * 4;               // B tile 32x64
        rbv[sIt] = *(const float4*)(Bp + (size_t)rB * ldb + c0 + cB);
    }

    const int m0 = warp * 16;
    for (int kt = 0; kt < 16; kt++) {
        // stage to smem with hi/lo split
        #pragma unroll
        for (int sIt = 0; sIt < 4; sIt++) {
            int idx = tid + sIt * 128;
            int r = idx >> 3, cc = (idx & 7) * 4;
            float4 v = ra[sIt];
            float* ph = &Ah[r * GA_S + cc];
            float* pl = &Al[r * GA_S + cc];
            { float hi = to_tf32(v.x); ph[0] = hi; pl[0] = to_tf32(v.x - hi); }
            { float hi = to_tf32(v.y); ph[1] = hi; pl[1] = to_tf32(v.y - hi); }
            { float hi = to_tf32(v.z); ph[2] = hi; pl[2] = to_tf32(v.z - hi); }
            { float hi = to_tf32(v.w); ph[3] = hi; pl[3] = to_tf32(v.w - hi); }
            int rB = idx >> 4, cB = (idx & 15) * 4;
            float4 w = rbv[sIt];
            float* qh = &Bh[rB * GB_S + cB];
            float* ql = &Bl[rB * GB_S + cB];
            { float hi = to_tf32(w.x); qh[0] = hi; ql[0] = to_tf32(w.x - hi); }
            { float hi = to_tf32(w.y); qh[1] = hi; ql[1] = to_tf32(w.y - hi); }
            { float hi = to_tf32(w.z); qh[2] = hi; ql[2] = to_tf32(w.z - hi); }
            { float hi = to_tf32(w.w); qh[3] = hi; ql[3] = to_tf32(w.w - hi); }
        }
        __syncthreads();
        if (kt < 15) {
            int k0 = (kt + 1) * 32;
            #pragma unroll
            for (int sIt = 0; sIt < 4; sIt++) {
                int idx = tid + sIt * 128;
                int r = idx >> 3, cc = (idx & 7) * 4;
                ra[sIt] = *(const float4*)(A + (size_t)(rb + r) * 512 + k0 + cc);
                int rB = idx >> 4, cB = (idx & 15) * 4;
                rbv[sIt] = *(const float4*)(Bp + (size_t)(k0 + rB) * ldb + c0 + cB);
            }
        }
        #pragma unroll
        for (int ks = 0; ks < 4; ks++) {
            const int kk = ks * 8;
            unsigned ah0 = __float_as_uint(Ah[(m0 + g) * GA_S + kk + t]);
            unsigned ah1 = __float_as_uint(Ah[(m0 + g + 8) * GA_S + kk + t]);
            unsigned ah2 = __float_as_uint(Ah[(m0 + g) * GA_S + kk + t + 4]);
            unsigned ah3 = __float_as_uint(Ah[(m0 + g + 8) * GA_S + kk + t + 4]);
            unsigned al0 = __float_as_uint(Al[(m0 + g) * GA_S + kk + t]);
            unsigned al1 = __float_as_uint(Al[(m0 + g + 8) * GA_S + kk + t]);
            unsigned al2 = __float_as_uint(Al[(m0 + g) * GA_S + kk + t + 4]);
            unsigned al3 = __float_as_uint(Al[(m0 + g + 8) * GA_S + kk + t + 4]);
            #pragma unroll
            for (int nb = 0; nb < 8; nb++) {
                unsigned bh0 = __float_as_uint(Bh[(kk + t) * GB_S + nb * 8 + g]);
                unsigned bh1 = __float_as_uint(Bh[(kk + t + 4) * GB_S + nb * 8 + g]);
                unsigned bl0 = __float_as_uint(Bl[(kk + t) * GB_S + nb * 8 + g]);
                unsigned bl1 = __float_as_uint(Bl[(kk + t + 4) * GB_S + nb * 8 + g]);
                mma8(acc[nb][0], acc[nb][1], acc[nb][2], acc[nb][3], ah0, ah1, ah2, ah3, bh0, bh1);
                mma8(acc[nb][0], acc[nb][1], acc[nb][2], acc[nb][3], ah0, ah1, ah2, ah3, bl0, bl1);
                mma8(acc[nb][0], acc[nb][1], acc[nb][2], acc[nb][3], al0, al1, al2, al3, bh0, bh1);
            }
        }
        __syncthreads();
    }

    // epilogue
    #pragma unroll
    for (int nb = 0; nb < 8; nb++) {
        int col = cb + nb * 8 + 2 * t;
        float b0v = 0.f, b1v = 0.f;
        if (mode == 1) { b0v = bias[col]; b1v = bias[col + 1]; }
        int r0 = rb + m0 + g;
        int r1 = r0 + 8;
        *(float2*)(C + (size_t)r0 * ldc + col) = make_float2(acc[nb][0] + b0v, acc[nb][1] + b1v);
        *(float2*)(C + (size_t)r1 * ldc + col) = make_float2(acc[nb][2] + b0v, acc[nb][3] + b1v);
    }
}

// =====================================================================
// Kernel 3: flash attention with additive bias. One CTA per (b,h,itile of 64).
// 128 threads / 4 warps; warp owns 16 query rows. j-tiles of 64, online softmax.
// =====================================================================
#define FS 68
__global__ __launch_bounds__(128) void k_flash() {
    extern __shared__ float sm[];
    float* Qs = sm;                       // 64*FS
    float* Ks = Qs + 64 * FS;
    float* Vs = Ks + 64 * FS;
    float* Bs = Vs + 64 * FS;
    float* Ps = Bs + 64 * FS;

    const int tid = threadIdx.x, lane = tid & 31, warp = tid >> 5;
    const int g = lane >> 2, t = lane & 3;
    const int it = blockIdx.x & 15;
    const int bh = blockIdx.x >> 4;
    const int b = bh >> 3, h = bh & 7;
    const int i0 = it * 64;
    const int m0 = warp * 16;
    const float NEG_INF = __int_as_float(0xff800000);

    const float* qbase = g_qkv + (size_t)b * NN * QKV_COLS;

    // load Q tile (x SCALE, tf32)
    for (int idx = tid; idx < 64 * 16; idx += 128) {
        int r = idx >> 4, cc = (idx & 15) * 4;
        float4 v = *(const float4*)(qbase + (size_t)(i0 + r) * QKV_COLS + h * 64 + cc);
        Qs[r * FS + cc + 0] = to_tf32(v.x * SCALE);
        Qs[r * FS + cc + 1] = to_tf32(v.y * SCALE);
        Qs[r * FS + cc + 2] = to_tf32(v.z * SCALE);
        Qs[r * FS + cc + 3] = to_tf32(v.w * SCALE);
    }

    float accO[8][4];
    #pragma unroll
    for (int i = 0; i < 8; i++)
        #pragma unroll
        for (int j = 0; j < 4; j++) accO[i][j] = 0.f;
    float mrow0 = NEG_INF, mrow1 = NEG_INF;
    float lrow0 = 0.f, lrow1 = 0.f;

    const float* brow = g_bias_t + ((size_t)bh * NN + i0) * NN;

    for (int jt = 0; jt < 16; jt++) {
        const int j0 = jt * 64;
        __syncthreads();
        // load K, V tiles (tf32) and bias tile (fp32)
        for (int idx = tid; idx < 64 * 16; idx += 128) {
            int r = idx >> 4, cc = (idx & 15) * 4;
            const float* kp = qbase + (size_t)(j0 + r) * QKV_COLS + INNER + h * 64 + cc;
            float4 kv = *(const float4*)kp;
            float4 vv = *(const float4*)(kp + INNER);
            Ks[r * FS + cc + 0] = to_tf32(kv.x);
            Ks[r * FS + cc + 1] = to_tf32(kv.y);
            Ks[r * FS + cc + 2] = to_tf32(kv.z);
            Ks[r * FS + cc + 3] = to_tf32(kv.w);
            Vs[r * FS + cc + 0] = to_tf32(vv.x);
            Vs[r * FS + cc + 1] = to_tf32(vv.y);
            Vs[r * FS + cc + 2] = to_tf32(vv.z);
            Vs[r * FS + cc + 3] = to_tf32(vv.w);
        }
        for (int idx = tid; idx < 64 * 16; idx += 128) {
            int r = idx >> 4, cc = (idx & 15) * 4;
            float4 bv = *(const float4*)(brow + (size_t)r * NN + j0 + cc);
            Bs[r * FS + cc + 0] = bv.x;
            Bs[r * FS + cc + 1] = bv.y;
            Bs[r * FS + cc + 2] = bv.z;
            Bs[r * FS + cc + 3] = bv.w;
        }
        __syncthreads();

        // S = Q @ K^T (tf32 mma), 16x64 per warp
        float s[8][4];
        #pragma unroll
        for (int i = 0; i < 8; i++)
            #pragma unroll
            for (int j = 0; j < 4; j++) s[i][j] = 0.f;
        #pragma unroll
        for (int ks = 0; ks < 8; ks++) {
            const int kk = ks * 8;
            unsigned a0 = __float_as_uint(Qs[(m0 + g) * FS + kk + t]);
            unsigned a1 = __float_as_uint(Qs[(m0 + g + 8) * FS + kk + t]);
            unsigned a2 = __float_as_uint(Qs[(m0 + g) * FS + kk + t + 4]);
            unsigned a3 = __float_as_uint(Qs[(m0 + g + 8) * FS + kk + t + 4]);
            #pragma unroll
            for (int nb = 0; nb < 8; nb++) {
                unsigned b0 = __float_as_uint(Ks[(nb * 8 + g) * FS + kk + t]);
                unsigned b1 = __float_as_uint(Ks[(nb * 8 + g) * FS + kk + t + 4]);
                mma8(s[nb][0], s[nb][1], s[nb][2], s[nb][3], a0, a1, a2, a3, b0, b1);
            }
        }
        // + bias (includes -1e30 mask), row max
        float mx0 = NEG_INF, mx1 = NEG_INF;
        #pragma unroll
        for (int nb = 0; nb < 8; nb++) {
            int c = nb * 8 + 2 * t;
            s[nb][0] += Bs[(m0 + g) * FS + c];
            s[nb][1] += Bs[(m0 + g) * FS + c + 1];
            s[nb][2] += Bs[(m0 + g + 8) * FS + c];
            s[nb][3] += Bs[(m0 + g + 8) * FS + c + 1];
            mx0 = fmaxf(mx0, fmaxf(s[nb][0], s[nb][1]));
            mx1 = fmaxf(mx1, fmaxf(s[nb][2], s[nb][3]));
        }
        mx0 = fmaxf(mx0, __shfl_xor_sync(0xffffffffu, mx0, 1));
        mx0 = fmaxf(mx0, __shfl_xor_sync(0xffffffffu, mx0, 2));
        mx1 = fmaxf(mx1, __shfl_xor_sync(0xffffffffu, mx1, 1));
        mx1 = fmaxf(mx1, __shfl_xor_sync(0xffffffffu, mx1, 2));

        float mn0 = fmaxf(mrow0, mx0), mn1 = fmaxf(mrow1, mx1);
        float al0 = ex2((mrow0 - mn0) * LOG2E);
        float al1 = ex2((mrow1 - mn1) * LOG2E);
        mrow0 = mn0;
        mrow1 = mn1;

        float sum0 = 0.f, sum1 = 0.f;
        #pragma unroll
        for (int nb = 0; nb < 8; nb++) {
            float p0 = ex2((s[nb][0] - mn0) * LOG2E);
            float p1 = ex2((s[nb][1] - mn0) * LOG2E);
            float p2 = ex2((s[nb][2] - mn1) * LOG2E);
            float p3 = ex2((s[nb][3] - mn1) * LOG2E);
            sum0 += p0 + p1;
            sum1 += p2 + p3;
            int c = nb * 8 + 2 * t;
            Ps[(m0 + g) * FS + c] = to_tf32(p0);
            Ps[(m0 + g) * FS + c + 1] = to_tf32(p1);
            Ps[(m0 + g + 8) * FS + c] = to_tf32(p2);
            Ps[(m0 + g + 8) * FS + c + 1] = to_tf32(p3);
        }
        sum0 += __shfl_xor_sync(0xffffffffu, sum0, 1);
        sum0 += __shfl_xor_sync(0xffffffffu, sum0, 2);
        sum1 += __shfl_xor_sync(0xffffffffu, sum1, 1);
        sum1 += __shfl_xor_sync(0xffffffffu, sum1, 2);
        lrow0 = lrow0 * al0 + sum0;
        lrow1 = lrow1 * al1 + sum1;

        #pragma unroll
        for (int nb = 0; nb < 8; nb++) {
            accO[nb][0] *= al0;
            accO[nb][1] *= al0;
            accO[nb][2] *= al1;
            accO[nb][3] *= al1;
        }
        __syncwarp();
        // O += P @ V
        #pragma unroll
        for (int ks = 0; ks < 8; ks++) {
            const int kk = ks * 8;
            unsigned a0 = __float_as_uint(Ps[(m0 + g) * FS + kk + t]);
            unsigned a1 = __float_as_uint(Ps[(m0 + g + 8) * FS + kk + t]);
            unsigned a2 = __float_as_uint(Ps[(m0 + g) * FS + kk + t + 4]);
            unsigned a3 = __float_as_uint(Ps[(m0 + g + 8) * FS + kk + t + 4]);
            #pragma unroll
            for (int nb = 0; nb < 8; nb++) {
                unsigned b0 = __float_as_uint(Vs[(kk + t) * FS + nb * 8 + g]);
                unsigned b1 = __float_as_uint(Vs[(kk + t + 4) * FS + nb * 8 + g]);
                mma8(accO[nb][0], accO[nb][1], accO[nb][2], accO[nb][3], a0, a1, a2, a3, b0, b1);
            }
        }
    }

    // write O / l  ->  g_att[(b,i),(h d)]
    float inv0 = 1.f / lrow0;
    float inv1 = 1.f / lrow1;
    #pragma unroll
    for (int nb = 0; nb < 8; nb++) {
        int col = h * 64 + nb * 8 + 2 * t;
        int r0 = b * NN + i0 + m0 + g;
        int r1 = r0 + 8;
        *(float2*)(g_att + (size_t)r0 * INNER + col) =
            make_float2(accO[nb][0] * inv0, accO[nb][1] * inv0);
        *(float2*)(g_att + (size_t)r1 * INNER + col) =
            make_float2(accO[nb][2] * inv1, accO[nb][3] * inv1);
    }
}

// =====================================================================
extern "C" void kernel_launch(void* const* d_in, const int* in_sizes, int n_in,
                              void* d_out, int out_size) {
    (void)in_sizes; (void)n_in; (void)out_size;
    const float* x = (const float*)d_in[0];
    const unsigned char* mask = (const unsigned char*)d_in[1];  // dtype probed on device
    const float* bias = (const float*)d_in[2];
    const float* Wq = (const float*)d_in[3];
    const float* Wkv = (const float*)d_in[4];
    const float* Wout = (const float*)d_in[5];
    const float* bout = (const float*)d_in[6];
    float* out = (float*)d_out;

    cudaFuncSetAttribute(k_flash, cudaFuncAttributeMaxDynamicSharedMemorySize, 5 * 64 * FS * 4);

    k_mask_expand<<<1, 256>>>(mask);
    k_bias_transpose<<<BB * NN, 256>>>(bias);
    k_gemm3x<<<dim3(QKV_COLS / 64, NROWS / 64), 128>>>(0, x, Wq, Wkv, nullptr, nullptr);
    k_flash<<<BB * HH * (NN / 64), 128, 5 * 64 * FS * 4>>>();
    k_gemm3x<<<dim3(DOUT / 64, NROWS / 64), 128>>>(1, nullptr, Wout, nullptr, bout, out);
}

// round 3
// speedup vs baseline: 1.6097x; 1.6097x over previous
#include <cuda_runtime.h>
#include <cuda_bf16.h>

#define BB 8
#define NN 1024
#define DIN 512
#define HH 8
#define INNER 512
#define DOUT 512
#define NROWS (BB*NN)            // 8192
#define QKV_COLS 1536
#define SCALE 0.125f
#define LOG2E 1.4426950408889634f

// ---- scratch (device globals; no runtime allocation) ----
__device__ float g_qkv[(size_t)NROWS * QKV_COLS];          // q|k|v per row, 48MB
__device__ float g_bias_t[(size_t)BB * HH * NN * NN];      // bias transposed+masked, 256MB
__device__ unsigned g_xh[(size_t)NROWS * (DIN/2)];         // x hi bf16 pairs
__device__ unsigned g_xl[(size_t)NROWS * (DIN/2)];
__device__ unsigned g_wqkvh[(size_t)(DIN/2) * QKV_COLS];   // [Wq|Wkv] packed hi
__device__ unsigned g_wqkvl[(size_t)(DIN/2) * QKV_COLS];
__device__ unsigned g_wouth[(size_t)(INNER/2) * DOUT];
__device__ unsigned g_woutl[(size_t)(INNER/2) * DOUT];
__device__ unsigned g_atth[(size_t)NROWS * (INNER/2)];     // attention out hi pairs
__device__ unsigned g_attl[(size_t)NROWS * (INNER/2)];
__device__ unsigned char g_maskb[BB * NN];

// ---- helpers ----
__device__ __forceinline__ float to_tf32(float x) {
    unsigned u;
    asm("cvt.rna.tf32.f32 %0, %1;" : "=r"(u) : "f"(x));
    return __uint_as_float(u);
}
__device__ __forceinline__ float ex2(float x) {
    float y;
    asm("ex2.approx.ftz.f32 %0, %1;" : "=f"(y) : "f"(x));
    return y;
}
// d[31:16]=bf16(a_hi), d[15:0]=bf16(a_lo)
__device__ __forceinline__ unsigned pack_bf16(float hi_elem, float lo_elem) {
    unsigned r;
    asm("cvt.rn.bf16x2.f32 %0, %1, %2;" : "=r"(r) : "f"(hi_elem), "f"(lo_elem));
    return r;
}
__device__ __forceinline__ void mma8(float& c0, float& c1, float& c2, float& c3,
                                     unsigned a0, unsigned a1, unsigned a2, unsigned a3,
                                     unsigned b0, unsigned b1) {
    asm volatile(
        "mma.sync.aligned.m16n8k8.row.col.f32.tf32.tf32.f32 "
        "{%0,%1,%2,%3},{%4,%5,%6,%7},{%8,%9},{%0,%1,%2,%3};\n"
        : "+f"(c0), "+f"(c1), "+f"(c2), "+f"(c3)
        : "r"(a0), "r"(a1), "r"(a2), "r"(a3), "r"(b0), "r"(b1));
}
__device__ __forceinline__ void mma16bf(float& c0, float& c1, float& c2, float& c3,
                                        unsigned a0, unsigned a1, unsigned a2, unsigned a3,
                                        unsigned b0, unsigned b1) {
    asm volatile(
        "mma.sync.aligned.m16n8k16.row.col.f32.bf16.bf16.f32 "
        "{%0,%1,%2,%3},{%4,%5,%6,%7},{%8,%9},{%0,%1,%2,%3};\n"
        : "+f"(c0), "+f"(c1), "+f"(c2), "+f"(c3)
        : "r"(a0), "r"(a1), "r"(a2), "r"(a3), "r"(b0), "r"(b1));
}

// =====================================================================
// Kernel 0: mask dtype detection + expansion (bool may arrive u8/i32/f32).
// =====================================================================
__global__ __launch_bounds__(256) void k_mask_expand(const unsigned char* __restrict__ m) {
    __shared__ int s_notI32, s_notF32;
    if (threadIdx.x == 0) { s_notI32 = 0; s_notF32 = 0; }
    __syncthreads();
    const unsigned* mw = (const unsigned*)m;
    int notI = 0, notF = 0;
    for (int i = threadIdx.x; i < BB * NN / 4; i += 256) {
        unsigned w = mw[i];
        if (w & 0xFFFFFF00u) notI = 1;
        if (w != 0u && w != 0x3F800000u) notF = 1;
    }
    if (notI) atomicOr(&s_notI32, 1);
    if (notF) atomicOr(&s_notF32, 1);
    __syncthreads();
    const int notI32 = s_notI32, notF32 = s_notF32;
    for (int i = threadIdx.x; i < BB * NN; i += 256) {
        unsigned char v;
        if (!notF32)      v = (((const unsigned*)m)[i] != 0u) ? 1 : 0;
        else if (!notI32) v = (((const int*)m)[i] != 0) ? 1 : 0;
        else              v = (m[i] != 0) ? 1 : 0;
        g_maskb[i] = v;
    }
}

// =====================================================================
// Kernel: split x (f32 [8192,512]) into packed bf16 hi/lo pair arrays.
// one u32 (k-pair) per thread.
// =====================================================================
__global__ __launch_bounds__(256) void k_split_x(const float* __restrict__ x) {
    int idx = blockIdx.x * 256 + threadIdx.x;            // over 8192*256 pairs
    float2 v = ((const float2*)x)[idx];
    unsigned hp = pack_bf16(v.y, v.x);
    float b0 = __uint_as_float(hp << 16);
    float b1 = __uint_as_float(hp & 0xFFFF0000u);
    unsigned lp = pack_bf16(v.y - b1, v.x - b0);
    g_xh[idx] = hp;
    g_xl[idx] = lp;
}

// =====================================================================
// Kernel: split weights into k-pair-packed bf16 hi/lo.
// wqkv[kp][n]: n<512 from Wq, else Wkv. wout[kp][n] from Wout.
// =====================================================================
__global__ __launch_bounds__(256) void k_split_w(const float* __restrict__ Wq,
                                                 const float* __restrict__ Wkv,
                                                 const float* __restrict__ Wout) {
    int idx = blockIdx.x * 256 + threadIdx.x;
    const int total1 = (DIN / 2) * QKV_COLS;             // 393216
    float a, b;
    unsigned* dh;
    unsigned* dl;
    int off;
    if (idx < total1) {
        int kp = idx / QKV_COLS, n = idx % QKV_COLS;
        if (n < 512) { a = Wq[(2 * kp) * 512 + n]; b = Wq[(2 * kp + 1) * 512 + n]; }
        else { int nn = n - 512; a = Wkv[(2 * kp) * 1024 + nn]; b = Wkv[(2 * kp + 1) * 1024 + nn]; }
        dh = g_wqkvh; dl = g_wqkvl; off = idx;
    } else {
        int j = idx - total1;                            // over 256*512
        int kp = j / DOUT, n = j % DOUT;
        a = Wout[(2 * kp) * DOUT + n];
        b = Wout[(2 * kp + 1) * DOUT + n];
        dh = g_wouth; dl = g_woutl; off = j;
    }
    unsigned hp = pack_bf16(b, a);
    float a0 = __uint_as_float(hp << 16);
    float b0 = __uint_as_float(hp & 0xFFFF0000u);
    unsigned lp = pack_bf16(b - b0, a - a0);
    dh[off] = hp;
    dl[off] = lp;
}

// =====================================================================
// Kernel 1: bias transpose + key mask fuse.
// bias_t[b,h,i,j] = mask[b,j] ? sim_bias[b,i,j,h] : -1e30
// =====================================================================
__global__ __launch_bounds__(256) void k_bias_transpose(const float* __restrict__ bias) {
    __shared__ float s[NN * 9];
    __shared__ unsigned char ms[NN];
    const int bi = blockIdx.x;
    const int b = bi >> 10;
    const float* src = bias + (size_t)bi * (NN * HH);

    #pragma unroll
    for (int sIt = 0; sIt < 8; sIt++) {
        int idx = threadIdx.x + sIt * 256;
        float4 v = *(const float4*)(src + idx * 4);
        int j = idx >> 1;
        int h = (idx & 1) * 4;
        s[j * 9 + h + 0] = v.x;
        s[j * 9 + h + 1] = v.y;
        s[j * 9 + h + 2] = v.z;
        s[j * 9 + h + 3] = v.w;
    }
    for (int j = threadIdx.x; j < NN; j += 256) ms[j] = g_maskb[b * NN + j];
    __syncthreads();

    const int i = bi & (NN - 1);
    #pragma unroll
    for (int h = 0; h < HH; h++) {
        float* dst = g_bias_t + (((size_t)(b * HH + h)) * NN + i) * NN;
        int j = threadIdx.x * 4;
        float4 o;
        o.x = ms[j + 0] ? s[(j + 0) * 9 + h] : -1e30f;
        o.y = ms[j + 1] ? s[(j + 1) * 9 + h] : -1e30f;
        o.z = ms[j + 2] ? s[(j + 2) * 9 + h] : -1e30f;
        o.w = ms[j + 3] ? s[(j + 3) * 9 + h] : -1e30f;
        *(float4*)(dst + j) = o;
    }
}

// =====================================================================
// GEMM, bf16 hi/lo 3-mma (m16n8k16), tile 128x64, 256 threads / 8 warps.
// mode 0: g_qkv[8192,1536] = x @ [Wq|Wkv]   (A = g_xh/g_xl)
// mode 1: out[8192,512]    = att @ Wout + bout (A = g_atth/g_attl)
// A packed u32 = bf16 pair (k, k+1), row-major [8192, 256].
// B packed u32 = bf16 pair (k, k+1) per col, [256, ncols].
// =====================================================================
#define GAS 20   // u32 row stride for A smem (16 data + pad, conflict-free frag loads)
#define GBS 72   // u32 row stride for B smem
__global__ __launch_bounds__(256, 2) void k_gemm_bf(int mode,
                                                    const float* __restrict__ bout,
                                                    float* __restrict__ Cout) {
    __shared__ unsigned sAh[128 * GAS], sAl[128 * GAS];
    __shared__ unsigned sBh[16 * GBS], sBl[16 * GBS];
    const int tid = threadIdx.x, lane = tid & 31, warp = tid >> 5;
    const int g = lane >> 2, t = lane & 3;
    const int cb = blockIdx.x * 64;
    const int rb = blockIdx.y * 128;
    const int m0 = warp * 16;

    const unsigned* Ah = (mode == 0) ? g_xh : g_atth;
    const unsigned* Al = (mode == 0) ? g_xl : g_attl;
    const unsigned* Bh = (mode == 0) ? g_wqkvh : g_wouth;
    const unsigned* Bl = (mode == 0) ? g_wqkvl : g_woutl;
    float* C = (mode == 0) ? g_qkv : Cout;
    const int ldc = (mode == 0) ? QKV_COLS : DOUT;
    const int ldb = ldc;   // B cols == C cols

    float acc[8][4];
    #pragma unroll
    for (int i = 0; i < 8; i++)
        #pragma unroll
        for (int j = 0; j < 4; j++) acc[i][j] = 0.f;

    for (int kt = 0; kt < 16; kt++) {
        const int kp0 = kt * 16;                         // k-pair offset
        __syncthreads();
        // A: 128 rows x 16 u32, as uint4: 512 per array, 2/thread
        #pragma unroll
        for (int sIt = 0; sIt < 2; sIt++) {
            int idx = tid + sIt * 256;
            int r = idx >> 2, c4 = (idx & 3) * 4;
            const size_t go = (size_t)(rb + r) * (DIN / 2) + kp0 + c4;
            uint4 vh = *(const uint4*)(Ah + go);
            uint4 vl = *(const uint4*)(Al + go);
            unsigned* ph = &sAh[r * GAS + c4];
            unsigned* pl = &sAl[r * GAS + c4];
            ph[0] = vh.x; ph[1] = vh.y; ph[2] = vh.z; ph[3] = vh.w;
            pl[0] = vl.x; pl[1] = vl.y; pl[2] = vl.z; pl[3] = vl.w;
        }
        // B: 16 k-pairs x 64 cols, 1 uint4/thread
        {
            int r = tid >> 4, c4 = (tid & 15) * 4;
            const size_t go = (size_t)(kp0 + r) * ldb + cb + c4;
            uint4 vh = *(const uint4*)(Bh + go);
            uint4 vl = *(const uint4*)(Bl + go);
            unsigned* ph = &sBh[r * GBS + c4];
            unsigned* pl = &sBl[r * GBS + c4];
            ph[0] = vh.x; ph[1] = vh.y; ph[2] = vh.z; ph[3] = vh.w;
            pl[0] = vl.x; pl[1] = vl.y; pl[2] = vl.z; pl[3] = vl.w;
        }
        __syncthreads();

        #pragma unroll
        for (int kc = 0; kc < 2; kc++) {
            const int ko = kc * 8;
            unsigned ah0 = sAh[(m0 + g) * GAS + ko + t];
            unsigned ah1 = sAh[(m0 + g + 8) * GAS + ko + t];
            unsigned ah2 = sAh[(m0 + g) * GAS + ko + t + 4];
            unsigned ah3 = sAh[(m0 + g + 8) * GAS + ko + t + 4];
            unsigned al0 = sAl[(m0 + g) * GAS + ko + t];
            unsigned al1 = sAl[(m0 + g + 8) * GAS + ko + t];
            unsigned al2 = sAl[(m0 + g) * GAS + ko + t + 4];
            unsigned al3 = sAl[(m0 + g + 8) * GAS + ko + t + 4];
            #pragma unroll
            for (int nb = 0; nb < 8; nb++) {
                unsigned bh0 = sBh[(ko + t) * GBS + nb * 8 + g];
                unsigned bh1 = sBh[(ko + t + 4) * GBS + nb * 8 + g];
                unsigned bl0 = sBl[(ko + t) * GBS + nb * 8 + g];
                unsigned bl1 = sBl[(ko + t + 4) * GBS + nb * 8 + g];
                mma16bf(acc[nb][0], acc[nb][1], acc[nb][2], acc[nb][3], ah0, ah1, ah2, ah3, bh0, bh1);
                mma16bf(acc[nb][0], acc[nb][1], acc[nb][2], acc[nb][3], ah0, ah1, ah2, ah3, bl0, bl1);
                mma16bf(acc[nb][0], acc[nb][1], acc[nb][2], acc[nb][3], al0, al1, al2, al3, bh0, bh1);
            }
        }
    }

    #pragma unroll
    for (int nb = 0; nb < 8; nb++) {
        int col = cb + nb * 8 + 2 * t;
        float b0v = 0.f, b1v = 0.f;
        if (mode == 1) { b0v = bout[col]; b1v = bout[col + 1]; }
        int r0 = rb + m0 + g;
        int r1 = r0 + 8;
        *(float2*)(C + (size_t)r0 * ldc + col) = make_float2(acc[nb][0] + b0v, acc[nb][1] + b1v);
        *(float2*)(C + (size_t)r1 * ldc + col) = make_float2(acc[nb][2] + b0v, acc[nb][3] + b1v);
    }
}

// =====================================================================
// Flash attention. One CTA per (b,h,i-tile of 128). 256 threads / 8 warps,
// warp owns 16 query rows. j-tiles of 64, online softmax.
// Bias is staged into the P buffer (dead during QK^T), then overwritten
// by P values at the same per-thread addresses (only __syncwarp needed).
// Epilogue emits attention output as packed bf16 hi/lo for the out-proj GEMM.
// =====================================================================
#define FS 68
__global__ __launch_bounds__(256, 2) void k_flash() {
    extern __shared__ float sm[];
    float* Qs = sm;                       // 128*FS
    float* Ks = Qs + 128 * FS;            // 64*FS
    float* Vs = Ks + 64 * FS;             // 64*FS
    float* Ps = Vs + 64 * FS;             // 128*FS  (bias staging + P)

    const int tid = threadIdx.x, lane = tid & 31, warp = tid >> 5;
    const int g = lane >> 2, t = lane & 3;
    const int it = blockIdx.x & 7;
    const int bh = blockIdx.x >> 3;
    const int b = bh >> 3, h = bh & 7;
    const int i0 = it * 128;
    const int m0 = warp * 16;
    const float NEG_INF = __int_as_float(0xff800000);

    const float* qbase = g_qkv + (size_t)b * NN * QKV_COLS;

    // load Q tile (x SCALE, tf32): 128 rows x 64 cols
    #pragma unroll
    for (int sIt = 0; sIt < 8; sIt++) {
        int idx = tid + sIt * 256;
        int r = idx >> 4, cc = (idx & 15) * 4;
        float4 v = *(const float4*)(qbase + (size_t)(i0 + r) * QKV_COLS + h * 64 + cc);
        Qs[r * FS + cc + 0] = to_tf32(v.x * SCALE);
        Qs[r * FS + cc + 1] = to_tf32(v.y * SCALE);
        Qs[r * FS + cc + 2] = to_tf32(v.z * SCALE);
        Qs[r * FS + cc + 3] = to_tf32(v.w * SCALE);
    }

    float accO[8][4];
    #pragma unroll
    for (int i = 0; i < 8; i++)
        #pragma unroll
        for (int j = 0; j < 4; j++) accO[i][j] = 0.f;
    float mrow0 = NEG_INF, mrow1 = NEG_INF;
    float lrow0 = 0.f, lrow1 = 0.f;

    const float* brow = g_bias_t + ((size_t)bh * NN + i0) * NN;

    for (int jt = 0; jt < 16; jt++) {
        const int j0 = jt * 64;
        __syncthreads();
        // K, V tiles (tf32)
        #pragma unroll
        for (int sIt = 0; sIt < 4; sIt++) {
            int idx = tid + sIt * 256;
            int r = idx >> 4, cc = (idx & 15) * 4;
            const float* kp = qbase + (size_t)(j0 + r) * QKV_COLS + INNER + h * 64 + cc;
            float4 kv = *(const float4*)kp;
            float4 vv = *(const float4*)(kp + INNER);
            Ks[r * FS + cc + 0] = to_tf32(kv.x);
            Ks[r * FS + cc + 1] = to_tf32(kv.y);
            Ks[r * FS + cc + 2] = to_tf32(kv.z);
            Ks[r * FS + cc + 3] = to_tf32(kv.w);
            Vs[r * FS + cc + 0] = to_tf32(vv.x);
            Vs[r * FS + cc + 1] = to_tf32(vv.y);
            Vs[r * FS + cc + 2] = to_tf32(vv.z);
            Vs[r * FS + cc + 3] = to_tf32(vv.w);
        }
        // bias tile (raw f32) -> Ps
        #pragma unroll
        for (int sIt = 0; sIt < 8; sIt++) {
            int idx = tid + sIt * 256;
            int r = idx >> 4, cc = (idx & 15) * 4;
            float4 bv = *(const float4*)(brow + (size_t)r * NN + j0 + cc);
            Ps[r * FS + cc + 0] = bv.x;
            Ps[r * FS + cc + 1] = bv.y;
            Ps[r * FS + cc + 2] = bv.z;
            Ps[r * FS + cc + 3] = bv.w;
        }
        __syncthreads();

        // S = Q @ K^T (tf32 mma), 16x64 per warp
        float s[8][4];
        #pragma unroll
        for (int i = 0; i < 8; i++)
            #pragma unroll
            for (int j = 0; j < 4; j++) s[i][j] = 0.f;
        #pragma unroll
        for (int ks = 0; ks < 8; ks++) {
            const int kk = ks * 8;
            unsigned a0 = __float_as_uint(Qs[(m0 + g) * FS + kk + t]);
            unsigned a1 = __float_as_uint(Qs[(m0 + g + 8) * FS + kk + t]);
            unsigned a2 = __float_as_uint(Qs[(m0 + g) * FS + kk + t + 4]);
            unsigned a3 = __float_as_uint(Qs[(m0 + g + 8) * FS + kk + t + 4]);
            #pragma unroll
            for (int nb = 0; nb < 8; nb++) {
                unsigned b0 = __float_as_uint(Ks[(nb * 8 + g) * FS + kk + t]);
                unsigned b1 = __float_as_uint(Ks[(nb * 8 + g) * FS + kk + t + 4]);
                mma8(s[nb][0], s[nb][1], s[nb][2], s[nb][3], a0, a1, a2, a3, b0, b1);
            }
        }
        // + bias (includes -1e30 mask) from Ps, row max
        float mx0 = NEG_INF, mx1 = NEG_INF;
        #pragma unroll
        for (int nb = 0; nb < 8; nb++) {
            int c = nb * 8 + 2 * t;
            float2 bA = *(float2*)&Ps[(m0 + g) * FS + c];
            float2 bB = *(float2*)&Ps[(m0 + g + 8) * FS + c];
            s[nb][0] += bA.x;
            s[nb][1] += bA.y;
            s[nb][2] += bB.x;
            s[nb][3] += bB.y;
            mx0 = fmaxf(mx0, fmaxf(s[nb][0], s[nb][1]));
            mx1 = fmaxf(mx1, fmaxf(s[nb][2], s[nb][3]));
        }
        mx0 = fmaxf(mx0, __shfl_xor_sync(0xffffffffu, mx0, 1));
        mx0 = fmaxf(mx0, __shfl_xor_sync(0xffffffffu, mx0, 2));
        mx1 = fmaxf(mx1, __shfl_xor_sync(0xffffffffu, mx1, 1));
        mx1 = fmaxf(mx1, __shfl_xor_sync(0xffffffffu, mx1, 2));

        float mn0 = fmaxf(mrow0, mx0), mn1 = fmaxf(mrow1, mx1);
        float al0 = ex2((mrow0 - mn0) * LOG2E);
        float al1 = ex2((mrow1 - mn1) * LOG2E);
        mrow0 = mn0;
        mrow1 = mn1;

        float sum0 = 0.f, sum1 = 0.f;
        #pragma unroll
        for (int nb = 0; nb < 8; nb++) {
            float p0 = ex2((s[nb][0] - mn0) * LOG2E);
            float p1 = ex2((s[nb][1] - mn0) * LOG2E);
            float p2 = ex2((s[nb][2] - mn1) * LOG2E);
            float p3 = ex2((s[nb][3] - mn1) * LOG2E);
            sum0 += p0 + p1;
            sum1 += p2 + p3;
            int c = nb * 8 + 2 * t;
            *(float2*)&Ps[(m0 + g) * FS + c] = make_float2(to_tf32(p0), to_tf32(p1));
            *(float2*)&Ps[(m0 + g + 8) * FS + c] = make_float2(to_tf32(p2), to_tf32(p3));
        }
        sum0 += __shfl_xor_sync(0xffffffffu, sum0, 1);
        sum0 += __shfl_xor_sync(0xffffffffu, sum0, 2);
        sum1 += __shfl_xor_sync(0xffffffffu, sum1, 1);
        sum1 += __shfl_xor_sync(0xffffffffu, sum1, 2);
        lrow0 = lrow0 * al0 + sum0;
        lrow1 = lrow1 * al1 + sum1;

        #pragma unroll
        for (int nb = 0; nb < 8; nb++) {
            accO[nb][0] *= al0;
            accO[nb][1] *= al0;
            accO[nb][2] *= al1;
            accO[nb][3] *= al1;
        }
        __syncwarp();
        // O += P @ V   (P rows are warp-private)
        #pragma unroll
        for (int ks = 0; ks < 8; ks++) {
            const int kk = ks * 8;
            unsigned a0 = __float_as_uint(Ps[(m0 + g) * FS + kk + t]);
            unsigned a1 = __float_as_uint(Ps[(m0 + g + 8) * FS + kk + t]);
            unsigned a2 = __float_as_uint(Ps[(m0 + g) * FS + kk + t + 4]);
            unsigned a3 = __float_as_uint(Ps[(m0 + g + 8) * FS + kk + t + 4]);
            #pragma unroll
            for (int nb = 0; nb < 8; nb++) {
                unsigned b0 = __float_as_uint(Vs[(kk + t) * FS + nb * 8 + g]);
                unsigned b1 = __float_as_uint(Vs[(kk + t + 4) * FS + nb * 8 + g]);
                mma8(accO[nb][0], accO[nb][1], accO[nb][2], accO[nb][3], a0, a1, a2, a3, b0, b1);
            }
        }
    }

    // epilogue: normalize, split to bf16 hi/lo pairs, write g_atth/g_attl
    float inv0 = 1.f / lrow0;
    float inv1 = 1.f / lrow1;
    #pragma unroll
    for (int nb = 0; nb < 8; nb++) {
        int cp = h * 32 + nb * 4 + t;                    // u32 (k-pair) column
        int r0 = b * NN + i0 + m0 + g;
        int r1 = r0 + 8;
        {
            float o0 = accO[nb][0] * inv0, o1 = accO[nb][1] * inv0;
            unsigned hp = pack_bf16(o1, o0);
            float c0 = __uint_as_float(hp << 16);
            float c1 = __uint_as_float(hp & 0xFFFF0000u);
            unsigned lp = pack_bf16(o1 - c1, o0 - c0);
            g_atth[(size_t)r0 * 256 + cp] = hp;
            g_attl[(size_t)r0 * 256 + cp] = lp;
        }
        {
            float o0 = accO[nb][2] * inv1, o1 = accO[nb][3] * inv1;
            unsigned hp = pack_bf16(o1, o0);
            float c0 = __uint_as_float(hp << 16);
            float c1 = __uint_as_float(hp & 0xFFFF0000u);
            unsigned lp = pack_bf16(o1 - c1, o0 - c0);
            g_atth[(size_t)r1 * 256 + cp] = hp;
            g_attl[(size_t)r1 * 256 + cp] = lp;
        }
    }
}

// =====================================================================
extern "C" void kernel_launch(void* const* d_in, const int* in_sizes, int n_in,
                              void* d_out, int out_size) {
    (void)in_sizes; (void)n_in; (void)out_size;
    const float* x = (const float*)d_in[0];
    const unsigned char* mask = (const unsigned char*)d_in[1];  // dtype probed on device
    const float* bias = (const float*)d_in[2];
    const float* Wq = (const float*)d_in[3];
    const float* Wkv = (const float*)d_in[4];
    const float* Wout = (const float*)d_in[5];
    const float* bout = (const float*)d_in[6];
    float* out = (float*)d_out;

    const int flash_smem = (128 + 64 + 64 + 128) * FS * 4;   // 104448
    cudaFuncSetAttribute(k_flash, cudaFuncAttributeMaxDynamicSharedMemorySize, flash_smem);

    k_mask_expand<<<1, 256>>>(mask);
    k_split_x<<<NROWS, 256>>>(x);
    k_split_w<<<2048, 256>>>(Wq, Wkv, Wout);
    k_bias_transpose<<<BB * NN, 256>>>(bias);
    k_gemm_bf<<<dim3(QKV_COLS / 64, NROWS / 128), 256>>>(0, nullptr, nullptr);
    k_flash<<<BB * HH * (NN / 128), 256, flash_smem>>>();
    k_gemm_bf<<<dim3(DOUT / 64, NROWS / 128), 256>>>(1, bout, out);
}

// round 5
// speedup vs baseline: 1.8338x; 1.1392x over previous
#include <cuda_runtime.h>
#include <cuda_bf16.h>

#define BB 8
#define NN 1024
#define DIN 512
#define HH 8
#define INNER 512
#define DOUT 512
#define NROWS (BB*NN)            // 8192
#define QKV_COLS 1536
#define SCALE 0.125f
#define LOG2E 1.4426950408889634f

// ---- scratch (device globals; no runtime allocation) ----
__device__ float g_qkv[(size_t)NROWS * QKV_COLS];           // q|k|v (tf32-rounded), 48MB
__device__ float g_bias_t[(size_t)BB * HH * NN * NN];       // bias transposed+masked f32, 256MB
__device__ unsigned g_xh[(size_t)NROWS * (DIN/2)];          // x hi bf16 pairs
__device__ unsigned g_xl[(size_t)NROWS * (DIN/2)];
__device__ unsigned g_wqkvh[(size_t)(DIN/2) * QKV_COLS];    // [SCALE*Wq | Wkv] packed hi
__device__ unsigned g_wqkvl[(size_t)(DIN/2) * QKV_COLS];
__device__ unsigned g_wouth[(size_t)(INNER/2) * DOUT];
__device__ unsigned g_woutl[(size_t)(INNER/2) * DOUT];
__device__ unsigned g_atth[(size_t)NROWS * (INNER/2)];      // attention out hi pairs
__device__ unsigned g_attl[(size_t)NROWS * (INNER/2)];
__device__ unsigned char g_maskb[BB * NN];

// ---- helpers ----
__device__ __forceinline__ float to_tf32(float x) {
    unsigned u;
    asm("cvt.rna.tf32.f32 %0, %1;" : "=r"(u) : "f"(x));
    return __uint_as_float(u);
}
__device__ __forceinline__ float ex2(float x) {
    float y;
    asm("ex2.approx.ftz.f32 %0, %1;" : "=f"(y) : "f"(x));
    return y;
}
// d[31:16]=bf16(hi_elem), d[15:0]=bf16(lo_elem)
__device__ __forceinline__ unsigned pack_bf16(float hi_elem, float lo_elem) {
    unsigned r;
    asm("cvt.rn.bf16x2.f32 %0, %1, %2;" : "=r"(r) : "f"(hi_elem), "f"(lo_elem));
    return r;
}
__device__ __forceinline__ void cp16(void* sp, const void* gp) {
    unsigned s = (unsigned)__cvta_generic_to_shared(sp);
    asm volatile("cp.async.cg.shared.global [%0], [%1], 16;\n" :: "r"(s), "l"(gp));
}
#define CP_COMMIT asm volatile("cp.async.commit_group;\n")
#define CP_WAIT0  asm volatile("cp.async.wait_group 0;\n")

__device__ __forceinline__ void mma8(float& c0, float& c1, float& c2, float& c3,
                                     unsigned a0, unsigned a1, unsigned a2, unsigned a3,
                                     unsigned b0, unsigned b1) {
    asm volatile(
        "mma.sync.aligned.m16n8k8.row.col.f32.tf32.tf32.f32 "
        "{%0,%1,%2,%3},{%4,%5,%6,%7},{%8,%9},{%0,%1,%2,%3};\n"
        : "+f"(c0), "+f"(c1), "+f"(c2), "+f"(c3)
        : "r"(a0), "r"(a1), "r"(a2), "r"(a3), "r"(b0), "r"(b1));
}
__device__ __forceinline__ void mma16bf(float& c0, float& c1, float& c2, float& c3,
                                        unsigned a0, unsigned a1, unsigned a2, unsigned a3,
                                        unsigned b0, unsigned b1) {
    asm volatile(
        "mma.sync.aligned.m16n8k16.row.col.f32.bf16.bf16.f32 "
        "{%0,%1,%2,%3},{%4,%5,%6,%7},{%8,%9},{%0,%1,%2,%3};\n"
        : "+f"(c0), "+f"(c1), "+f"(c2), "+f"(c3)
        : "r"(a0), "r"(a1), "r"(a2), "r"(a3), "r"(b0), "r"(b1));
}

// =====================================================================
// Kernel 0: mask dtype detection + expansion (bool may arrive u8/i32/f32).
// =====================================================================
__global__ __launch_bounds__(256) void k_mask_expand(const unsigned char* __restrict__ m) {
    __shared__ int s_notI32, s_notF32;
    if (threadIdx.x == 0) { s_notI32 = 0; s_notF32 = 0; }
    __syncthreads();
    const unsigned* mw = (const unsigned*)m;
    int notI = 0, notF = 0;
    for (int i = threadIdx.x; i < BB * NN / 4; i += 256) {
        unsigned w = mw[i];
        if (w & 0xFFFFFF00u) notI = 1;
        if (w != 0u && w != 0x3F800000u) notF = 1;
    }
    if (notI) atomicOr(&s_notI32, 1);
    if (notF) atomicOr(&s_notF32, 1);
    __syncthreads();
    const int notI32 = s_notI32, notF32 = s_notF32;
    for (int i = threadIdx.x; i < BB * NN; i += 256) {
        unsigned char v;
        if (!notF32)      v = (((const unsigned*)m)[i] != 0u) ? 1 : 0;
        else if (!notI32) v = (((const int*)m)[i] != 0) ? 1 : 0;
        else              v = (m[i] != 0) ? 1 : 0;
        g_maskb[i] = v;
    }
}

// =====================================================================
// split x (f32 [8192,512]) into packed bf16 hi/lo pair arrays.
// =====================================================================
__global__ __launch_bounds__(256) void k_split_x(const float* __restrict__ x) {
    int idx = blockIdx.x * 256 + threadIdx.x;
    float2 v = ((const float2*)x)[idx];
    unsigned hp = pack_bf16(v.y, v.x);
    float b0 = __uint_as_float(hp << 16);
    float b1 = __uint_as_float(hp & 0xFFFF0000u);
    unsigned lp = pack_bf16(v.y - b1, v.x - b0);
    g_xh[idx] = hp;
    g_xl[idx] = lp;
}

// =====================================================================
// split weights; SCALE folded into Wq.
// =====================================================================
__global__ __launch_bounds__(256) void k_split_w(const float* __restrict__ Wq,
                                                 const float* __restrict__ Wkv,
                                                 const float* __restrict__ Wout) {
    int idx = blockIdx.x * 256 + threadIdx.x;
    const int total1 = (DIN / 2) * QKV_COLS;             // 393216
    float a, b;
    unsigned* dh;
    unsigned* dl;
    int off;
    if (idx < total1) {
        int kp = idx / QKV_COLS, n = idx % QKV_COLS;
        if (n < 512) {
            a = Wq[(2 * kp) * 512 + n] * SCALE;
            b = Wq[(2 * kp + 1) * 512 + n] * SCALE;
        } else {
            int nn = n - 512;
            a = Wkv[(2 * kp) * 1024 + nn];
            b = Wkv[(2 * kp + 1) * 1024 + nn];
        }
        dh = g_wqkvh; dl = g_wqkvl; off = idx;
    } else {
        int j = idx - total1;
        int kp = j / DOUT, n = j % DOUT;
        a = Wout[(2 * kp) * DOUT + n];
        b = Wout[(2 * kp + 1) * DOUT + n];
        dh = g_wouth; dl = g_woutl; off = j;
    }
    unsigned hp = pack_bf16(b, a);
    float a0 = __uint_as_float(hp << 16);
    float b0 = __uint_as_float(hp & 0xFFFF0000u);
    unsigned lp = pack_bf16(b - b0, a - a0);
    dh[off] = hp;
    dl[off] = lp;
}

// =====================================================================
// bias transpose + key-mask fuse, f32 output (bf16 proved too lossy: scores
// need full precision on the additive bias).
// bias_t[b,h,i,j] = mask[b,j] ? sim_bias[b,i,j,h] : -1e30
// =====================================================================
__global__ __launch_bounds__(256) void k_bias_transpose(const float* __restrict__ bias) {
    __shared__ float s[NN * 9];
    __shared__ unsigned char ms[NN];
    const int bi = blockIdx.x;
    const int b = bi >> 10;
    const float* src = bias + (size_t)bi * (NN * HH);

    #pragma unroll
    for (int sIt = 0; sIt < 8; sIt++) {
        int idx = threadIdx.x + sIt * 256;
        float4 v = *(const float4*)(src + idx * 4);
        int j = idx >> 1;
        int h = (idx & 1) * 4;
        s[j * 9 + h + 0] = v.x;
        s[j * 9 + h + 1] = v.y;
        s[j * 9 + h + 2] = v.z;
        s[j * 9 + h + 3] = v.w;
    }
    for (int j = threadIdx.x; j < NN; j += 256) ms[j] = g_maskb[b * NN + j];
    __syncthreads();

    const int i = bi & (NN - 1);
    #pragma unroll
    for (int h = 0; h < HH; h++) {
        float* dst = g_bias_t + (((size_t)(b * HH + h)) * NN + i) * NN;
        int j = threadIdx.x * 4;
        float4 o;
        o.x = ms[j + 0] ? s[(j + 0) * 9 + h] : -1e30f;
        o.y = ms[j + 1] ? s[(j + 1) * 9 + h] : -1e30f;
        o.z = ms[j + 2] ? s[(j + 2) * 9 + h] : -1e30f;
        o.w = ms[j + 3] ? s[(j + 3) * 9 + h] : -1e30f;
        *(float4*)(dst + j) = o;
    }
}

// =====================================================================
// GEMM, bf16 hi/lo 3-mma (m16n8k16), tile 128x64, 256 thr / 8 warps,
// 2-stage cp.async double buffer.
// mode 0: g_qkv = x @ [SCALE*Wq|Wkv], epilogue tf32-rounds output.
// mode 1: out   = att @ Wout + bout.
// =====================================================================
#define GAS 20   // u32 row stride A smem
#define GBS 72   // u32 row stride B smem
#define GEMM_SMEM ((2*128*GAS*2 + 2*16*GBS*2) * 4)   // 59392 bytes
__global__ __launch_bounds__(256, 2) void k_gemm_bf(int mode,
                                                    const float* __restrict__ bout,
                                                    float* __restrict__ Cout) {
    extern __shared__ unsigned smg[];
    unsigned* sAh = smg;                          // 2 stages x 128*GAS
    unsigned* sAl = sAh + 2 * 128 * GAS;
    unsigned* sBh = sAl + 2 * 128 * GAS;          // 2 stages x 16*GBS
    unsigned* sBl = sBh + 2 * 16 * GBS;

    const int tid = threadIdx.x, lane = tid & 31, warp = tid >> 5;
    const int g = lane >> 2, t = lane & 3;
    const int cb = blockIdx.x * 64;
    const int rb = blockIdx.y * 128;
    const int m0 = warp * 16;

    const unsigned* Ah = (mode == 0) ? g_xh : g_atth;
    const unsigned* Al = (mode == 0) ? g_xl : g_attl;
    const unsigned* Bh = (mode == 0) ? g_wqkvh : g_wouth;
    const unsigned* Bl = (mode == 0) ? g_wqkvl : g_woutl;
    float* C = (mode == 0) ? g_qkv : Cout;
    const int ldc = (mode == 0) ? QKV_COLS : DOUT;
    const int ldb = ldc;

    const int ar0 = tid >> 2, ac4 = (tid & 3) * 4;
    const int br = tid >> 4, bc4 = (tid & 15) * 4;

    auto load_stage = [&](int st, int kt) {
        const int kp0 = kt * 16;
        unsigned* pAh = sAh + st * 128 * GAS;
        unsigned* pAl = sAl + st * 128 * GAS;
        #pragma unroll
        for (int sIt = 0; sIt < 2; sIt++) {
            int r = ar0 + sIt * 64;
            size_t go = (size_t)(rb + r) * 256 + kp0 + ac4;
            cp16(&pAh[r * GAS + ac4], Ah + go);
            cp16(&pAl[r * GAS + ac4], Al + go);
        }
        size_t go = (size_t)(kp0 + br) * ldb + cb + bc4;
        cp16(&sBh[st * 16 * GBS + br * GBS + bc4], Bh + go);
        cp16(&sBl[st * 16 * GBS + br * GBS + bc4], Bl + go);
    };

    float acc[8][4];
    #pragma unroll
    for (int i = 0; i < 8; i++)
        #pragma unroll
        for (int j = 0; j < 4; j++) acc[i][j] = 0.f;

    load_stage(0, 0);
    CP_COMMIT;

    for (int kt = 0; kt < 16; kt++) {
        CP_WAIT0;
        __syncthreads();
        if (kt < 15) { load_stage((kt + 1) & 1, kt + 1); CP_COMMIT; }

        const unsigned* pAh = sAh + (kt & 1) * 128 * GAS;
        const unsigned* pAl = sAl + (kt & 1) * 128 * GAS;
        const unsigned* pBh = sBh + (kt & 1) * 16 * GBS;
        const unsigned* pBl = sBl + (kt & 1) * 16 * GBS;

        #pragma unroll
        for (int kc = 0; kc < 2; kc++) {
            const int ko = kc * 8;
            unsigned ah0 = pAh[(m0 + g) * GAS + ko + t];
            unsigned ah1 = pAh[(m0 + g + 8) * GAS + ko + t];
            unsigned ah2 = pAh[(m0 + g) * GAS + ko + t + 4];
            unsigned ah3 = pAh[(m0 + g + 8) * GAS + ko + t + 4];
            unsigned al0 = pAl[(m0 + g) * GAS + ko + t];
            unsigned al1 = pAl[(m0 + g + 8) * GAS + ko + t];
            unsigned al2 = pAl[(m0 + g) * GAS + ko + t + 4];
            unsigned al3 = pAl[(m0 + g + 8) * GAS + ko + t + 4];
            #pragma unroll
            for (int nb = 0; nb < 8; nb++) {
                unsigned bh0 = pBh[(ko + t) * GBS + nb * 8 + g];
                unsigned bh1 = pBh[(ko + t + 4) * GBS + nb * 8 + g];
                unsigned bl0 = pBl[(ko + t) * GBS + nb * 8 + g];
                unsigned bl1 = pBl[(ko + t + 4) * GBS + nb * 8 + g];
                mma16bf(acc[nb][0], acc[nb][1], acc[nb][2], acc[nb][3], ah0, ah1, ah2, ah3, bh0, bh1);
                mma16bf(acc[nb][0], acc[nb][1], acc[nb][2], acc[nb][3], ah0, ah1, ah2, ah3, bl0, bl1);
                mma16bf(acc[nb][0], acc[nb][1], acc[nb][2], acc[nb][3], al0, al1, al2, al3, bh0, bh1);
            }
        }
        __syncthreads();
    }

    #pragma unroll
    for (int nb = 0; nb < 8; nb++) {
        int col = cb + nb * 8 + 2 * t;
        int r0 = rb + m0 + g;
        int r1 = r0 + 8;
        if (mode == 0) {
            *(float2*)(C + (size_t)r0 * ldc + col) = make_float2(to_tf32(acc[nb][0]), to_tf32(acc[nb][1]));
            *(float2*)(C + (size_t)r1 * ldc + col) = make_float2(to_tf32(acc[nb][2]), to_tf32(acc[nb][3]));
        } else {
            float b0v = bout[col], b1v = bout[col + 1];
            *(float2*)(C + (size_t)r0 * ldc + col) = make_float2(acc[nb][0] + b0v, acc[nb][1] + b1v);
            *(float2*)(C + (size_t)r1 * ldc + col) = make_float2(acc[nb][2] + b0v, acc[nb][3] + b1v);
        }
    }
}

// =====================================================================
// Flash attention. CTA = (b,h,i-tile 128). 256 thr / 8 warps.
// All tiles via cp.async (values pre-rounded tf32 by the QKV GEMM; SCALE
// pre-folded into Wq). f32 bias overlays the P buffer; consume->overwrite is
// same-thread same-address, so __syncwarp suffices.
// =====================================================================
#define FS 68
__global__ __launch_bounds__(256, 2) void k_flash() {
    extern __shared__ float sm[];
    float* Qs = sm;                       // 128*FS
    float* Ks = Qs + 128 * FS;            // 64*FS
    float* Vs = Ks + 64 * FS;             // 64*FS
    float* Ps = Vs + 64 * FS;             // 128*FS  (bias f32 overlay + P)

    const int tid = threadIdx.x, lane = tid & 31, warp = tid >> 5;
    const int g = lane >> 2, t = lane & 3;
    const int it = blockIdx.x & 7;
    const int bh = blockIdx.x >> 3;
    const int b = bh >> 3, h = bh & 7;
    const int i0 = it * 128;
    const int m0 = warp * 16;
    const float NEG_INF = __int_as_float(0xff800000);

    const float* qbase = g_qkv + (size_t)b * NN * QKV_COLS;
    const float* bbase = g_bias_t + ((size_t)bh * NN + i0) * NN;

    // Q tile via cp.async
    {
        int r = tid >> 4, c4 = (tid & 15) * 4;
        #pragma unroll
        for (int sIt = 0; sIt < 8; sIt++) {
            cp16(&Qs[(r + sIt * 16) * FS + c4],
                 qbase + (size_t)(i0 + r + sIt * 16) * QKV_COLS + h * 64 + c4);
        }
    }
    CP_COMMIT;

    float accO[8][4];
    #pragma unroll
    for (int i = 0; i < 8; i++)
        #pragma unroll
        for (int j = 0; j < 4; j++) accO[i][j] = 0.f;
    float mrow0 = NEG_INF, mrow1 = NEG_INF;
    float lrow0 = 0.f, lrow1 = 0.f;

    const int kvr = tid >> 4, kvc4 = (tid & 15) * 4;

    for (int jt = 0; jt < 16; jt++) {
        const int j0 = jt * 64;
        __syncthreads();                                   // Ps/Ks/Vs free
        #pragma unroll
        for (int sIt = 0; sIt < 4; sIt++) {
            int r = kvr + sIt * 16;
            const float* kp = qbase + (size_t)(j0 + r) * QKV_COLS + 512 + h * 64 + kvc4;
            cp16(&Ks[r * FS + kvc4], kp);
            cp16(&Vs[r * FS + kvc4], kp + 512);
        }
        #pragma unroll
        for (int sIt = 0; sIt < 8; sIt++) {
            int r = kvr + sIt * 16;
            cp16(&Ps[r * FS + kvc4], bbase + (size_t)r * NN + j0 + kvc4);
        }
        CP_COMMIT;
        CP_WAIT0;
        __syncthreads();

        // S = Q @ K^T
        float s[8][4];
        #pragma unroll
        for (int i = 0; i < 8; i++)
            #pragma unroll
            for (int j = 0; j < 4; j++) s[i][j] = 0.f;
        #pragma unroll
        for (int ks = 0; ks < 8; ks++) {
            const int kk = ks * 8;
            unsigned a0 = __float_as_uint(Qs[(m0 + g) * FS + kk + t]);
            unsigned a1 = __float_as_uint(Qs[(m0 + g + 8) * FS + kk + t]);
            unsigned a2 = __float_as_uint(Qs[(m0 + g) * FS + kk + t + 4]);
            unsigned a3 = __float_as_uint(Qs[(m0 + g + 8) * FS + kk + t + 4]);
            #pragma unroll
            for (int nb = 0; nb < 8; nb++) {
                unsigned b0 = __float_as_uint(Ks[(nb * 8 + g) * FS + kk + t]);
                unsigned b1 = __float_as_uint(Ks[(nb * 8 + g) * FS + kk + t + 4]);
                mma8(s[nb][0], s[nb][1], s[nb][2], s[nb][3], a0, a1, a2, a3, b0, b1);
            }
        }
        // + bias (f32, includes -1e30 mask), row max
        float mx0 = NEG_INF, mx1 = NEG_INF;
        #pragma unroll
        for (int nb = 0; nb < 8; nb++) {
            int c = nb * 8 + 2 * t;
            float2 bA = *(float2*)&Ps[(m0 + g) * FS + c];
            float2 bB = *(float2*)&Ps[(m0 + g + 8) * FS + c];
            s[nb][0] += bA.x;
            s[nb][1] += bA.y;
            s[nb][2] += bB.x;
            s[nb][3] += bB.y;
            mx0 = fmaxf(mx0, fmaxf(s[nb][0], s[nb][1]));
            mx1 = fmaxf(mx1, fmaxf(s[nb][2], s[nb][3]));
        }
        mx0 = fmaxf(mx0, __shfl_xor_sync(0xffffffffu, mx0, 1));
        mx0 = fmaxf(mx0, __shfl_xor_sync(0xffffffffu, mx0, 2));
        mx1 = fmaxf(mx1, __shfl_xor_sync(0xffffffffu, mx1, 1));
        mx1 = fmaxf(mx1, __shfl_xor_sync(0xffffffffu, mx1, 2));

        float mn0 = fmaxf(mrow0, mx0), mn1 = fmaxf(mrow1, mx1);
        float al0 = ex2((mrow0 - mn0) * LOG2E);
        float al1 = ex2((mrow1 - mn1) * LOG2E);
        mrow0 = mn0;
        mrow1 = mn1;

        float sum0 = 0.f, sum1 = 0.f;
        #pragma unroll
        for (int nb = 0; nb < 8; nb++) {
            float p0 = ex2((s[nb][0] - mn0) * LOG2E);
            float p1 = ex2((s[nb][1] - mn0) * LOG2E);
            float p2 = ex2((s[nb][2] - mn1) * LOG2E);
            float p3 = ex2((s[nb][3] - mn1) * LOG2E);
            sum0 += p0 + p1;
            sum1 += p2 + p3;
            int c = nb * 8 + 2 * t;
            *(float2*)&Ps[(m0 + g) * FS + c] = make_float2(to_tf32(p0), to_tf32(p1));
            *(float2*)&Ps[(m0 + g + 8) * FS + c] = make_float2(to_tf32(p2), to_tf32(p3));
        }
        sum0 += __shfl_xor_sync(0xffffffffu, sum0, 1);
        sum0 += __shfl_xor_sync(0xffffffffu, sum0, 2);
        sum1 += __shfl_xor_sync(0xffffffffu, sum1, 1);
        sum1 += __shfl_xor_sync(0xffffffffu, sum1, 2);
        lrow0 = lrow0 * al0 + sum0;
        lrow1 = lrow1 * al1 + sum1;

        #pragma unroll
        for (int nb = 0; nb < 8; nb++) {
            accO[nb][0] *= al0;
            accO[nb][1] *= al0;
            accO[nb][2] *= al1;
            accO[nb][3] *= al1;
        }
        __syncwarp();
        // O += P @ V   (P rows warp-private)
        #pragma unroll
        for (int ks = 0; ks < 8; ks++) {
            const int kk = ks * 8;
            unsigned a0 = __float_as_uint(Ps[(m0 + g) * FS + kk + t]);
            unsigned a1 = __float_as_uint(Ps[(m0 + g + 8) * FS + kk + t]);
            unsigned a2 = __float_as_uint(Ps[(m0 + g) * FS + kk + t + 4]);
            unsigned a3 = __float_as_uint(Ps[(m0 + g + 8) * FS + kk + t + 4]);
            #pragma unroll
            for (int nb = 0; nb < 8; nb++) {
                unsigned b0 = __float_as_uint(Vs[(kk + t) * FS + nb * 8 + g]);
                unsigned b1 = __float_as_uint(Vs[(kk + t + 4) * FS + nb * 8 + g]);
                mma8(accO[nb][0], accO[nb][1], accO[nb][2], accO[nb][3], a0, a1, a2, a3, b0, b1);
            }
        }
    }

    // epilogue: normalize, split to bf16 hi/lo pairs
    float inv0 = 1.f / lrow0;
    float inv1 = 1.f / lrow1;
    #pragma unroll
    for (int nb = 0; nb < 8; nb++) {
        int cp = h * 32 + nb * 4 + t;
        int r0 = b * NN + i0 + m0 + g;
        int r1 = r0 + 8;
        {
            float o0 = accO[nb][0] * inv0, o1 = accO[nb][1] * inv0;
            unsigned hp = pack_bf16(o1, o0);
            float c0 = __uint_as_float(hp << 16);
            float c1 = __uint_as_float(hp & 0xFFFF0000u);
            unsigned lp = pack_bf16(o1 - c1, o0 - c0);
            g_atth[(size_t)r0 * 256 + cp] = hp;
            g_attl[(size_t)r0 * 256 + cp] = lp;
        }
        {
            float o0 = accO[nb][2] * inv1, o1 = accO[nb][3] * inv1;
            unsigned hp = pack_bf16(o1, o0);
            float c0 = __uint_as_float(hp << 16);
            float c1 = __uint_as_float(hp & 0xFFFF0000u);
            unsigned lp = pack_bf16(o1 - c1, o0 - c0);
            g_atth[(size_t)r1 * 256 + cp] = hp;
            g_attl[(size_t)r1 * 256 + cp] = lp;
        }
    }
}

// =====================================================================
extern "C" void kernel_launch(void* const* d_in, const int* in_sizes, int n_in,
                              void* d_out, int out_size) {
    (void)in_sizes; (void)n_in; (void)out_size;
    const float* x = (const float*)d_in[0];
    const unsigned char* mask = (const unsigned char*)d_in[1];
    const float* bias = (const float*)d_in[2];
    const float* Wq = (const float*)d_in[3];
    const float* Wkv = (const float*)d_in[4];
    const float* Wout = (const float*)d_in[5];
    const float* bout = (const float*)d_in[6];
    float* out = (float*)d_out;

    const int flash_smem = (128 + 64 + 64 + 128) * FS * 4;   // 104448
    cudaFuncSetAttribute(k_flash, cudaFuncAttributeMaxDynamicSharedMemorySize, flash_smem);
    cudaFuncSetAttribute(k_gemm_bf, cudaFuncAttributeMaxDynamicSharedMemorySize, GEMM_SMEM);

    k_mask_expand<<<1, 256>>>(mask);
    k_split_x<<<NROWS, 256>>>(x);
    k_split_w<<<2048, 256>>>(Wq, Wkv, Wout);
    k_bias_transpose<<<BB * NN, 256>>>(bias);
    k_gemm_bf<<<dim3(QKV_COLS / 64, NROWS / 128), 256, GEMM_SMEM>>>(0, nullptr, nullptr);
    k_flash<<<BB * HH * (NN / 128), 256, flash_smem>>>();
    k_gemm_bf<<<dim3(DOUT / 64, NROWS / 128), 256, GEMM_SMEM>>>(1, bout, out);
}

// round 6
// speedup vs baseline: 1.9297x; 1.0523x over previous
#include <cuda_runtime.h>
#include <cuda_bf16.h>

#define BB 8
#define NN 1024
#define DIN 512
#define HH 8
#define INNER 512
#define DOUT 512
#define NROWS (BB*NN)            // 8192
#define QKV_COLS 1536
#define SCALE 0.125f
#define LOG2E 1.4426950408889634f

// ---- scratch (device globals; no runtime allocation) ----
__device__ float g_qkv[(size_t)NROWS * QKV_COLS];           // q|k|v (tf32-rounded), 48MB
__device__ float g_bias_t[(size_t)BB * HH * NN * NN];       // bias transposed+masked f32, 256MB
__device__ unsigned g_xh[(size_t)NROWS * (DIN/2)];          // x hi bf16 pairs
__device__ unsigned g_xl[(size_t)NROWS * (DIN/2)];
__device__ unsigned g_wqkvh[(size_t)(DIN/2) * QKV_COLS];    // [SCALE*Wq | Wkv] packed hi
__device__ unsigned g_wqkvl[(size_t)(DIN/2) * QKV_COLS];
__device__ unsigned g_wouth[(size_t)(INNER/2) * DOUT];
__device__ unsigned g_woutl[(size_t)(INNER/2) * DOUT];
__device__ unsigned g_atth[(size_t)NROWS * (INNER/2)];      // attention out hi pairs
__device__ unsigned g_attl[(size_t)NROWS * (INNER/2)];
__device__ unsigned char g_maskb[BB * NN];

// ---- helpers ----
__device__ __forceinline__ float to_tf32(float x) {
    unsigned u;
    asm("cvt.rna.tf32.f32 %0, %1;" : "=r"(u) : "f"(x));
    return __uint_as_float(u);
}
__device__ __forceinline__ float ex2(float x) {
    float y;
    asm("ex2.approx.ftz.f32 %0, %1;" : "=f"(y) : "f"(x));
    return y;
}
// d[31:16]=bf16(hi_elem), d[15:0]=bf16(lo_elem)
__device__ __forceinline__ unsigned pack_bf16(float hi_elem, float lo_elem) {
    unsigned r;
    asm("cvt.rn.bf16x2.f32 %0, %1, %2;" : "=r"(r) : "f"(hi_elem), "f"(lo_elem));
    return r;
}
__device__ __forceinline__ void cp16(void* sp, const void* gp) {
    unsigned s = (unsigned)__cvta_generic_to_shared(sp);
    asm volatile("cp.async.cg.shared.global [%0], [%1], 16;\n" :: "r"(s), "l"(gp));
}
#define CP_COMMIT asm volatile("cp.async.commit_group;\n")
#define CP_WAIT0  asm volatile("cp.async.wait_group 0;\n")
#define CP_WAIT1  asm volatile("cp.async.wait_group 1;\n")

__device__ __forceinline__ void mma8(float& c0, float& c1, float& c2, float& c3,
                                     unsigned a0, unsigned a1, unsigned a2, unsigned a3,
                                     unsigned b0, unsigned b1) {
    asm volatile(
        "mma.sync.aligned.m16n8k8.row.col.f32.tf32.tf32.f32 "
        "{%0,%1,%2,%3},{%4,%5,%6,%7},{%8,%9},{%0,%1,%2,%3};\n"
        : "+f"(c0), "+f"(c1), "+f"(c2), "+f"(c3)
        : "r"(a0), "r"(a1), "r"(a2), "r"(a3), "r"(b0), "r"(b1));
}
__device__ __forceinline__ void mma16bf(float& c0, float& c1, float& c2, float& c3,
                                        unsigned a0, unsigned a1, unsigned a2, unsigned a3,
                                        unsigned b0, unsigned b1) {
    asm volatile(
        "mma.sync.aligned.m16n8k16.row.col.f32.bf16.bf16.f32 "
        "{%0,%1,%2,%3},{%4,%5,%6,%7},{%8,%9},{%0,%1,%2,%3};\n"
        : "+f"(c0), "+f"(c1), "+f"(c2), "+f"(c3)
        : "r"(a0), "r"(a1), "r"(a2), "r"(a3), "r"(b0), "r"(b1));
}

// =====================================================================
// k_prep: fused  [CTA 0] mask dtype detect+expand
//                [CTA 1..8192] split x into bf16 hi/lo pairs
//                [CTA 8193..10240] split weights (SCALE folded into Wq)
// =====================================================================
__global__ __launch_bounds__(256) void k_prep(const unsigned char* __restrict__ m,
                                              const float* __restrict__ x,
                                              const float* __restrict__ Wq,
                                              const float* __restrict__ Wkv,
                                              const float* __restrict__ Wout) {
    const int bid = blockIdx.x;
    if (bid == 0) {
        // ---- mask expansion (bool may arrive u8/i32/f32) ----
        __shared__ int s_notI32, s_notF32;
        if (threadIdx.x == 0) { s_notI32 = 0; s_notF32 = 0; }
        __syncthreads();
        const unsigned* mw = (const unsigned*)m;
        int notI = 0, notF = 0;
        for (int i = threadIdx.x; i < BB * NN / 4; i += 256) {
            unsigned w = mw[i];
            if (w & 0xFFFFFF00u) notI = 1;
            if (w != 0u && w != 0x3F800000u) notF = 1;
        }
        if (notI) atomicOr(&s_notI32, 1);
        if (notF) atomicOr(&s_notF32, 1);
        __syncthreads();
        const int notI32 = s_notI32, notF32 = s_notF32;
        for (int i = threadIdx.x; i < BB * NN; i += 256) {
            unsigned char v;
            if (!notF32)      v = (((const unsigned*)m)[i] != 0u) ? 1 : 0;
            else if (!notI32) v = (((const int*)m)[i] != 0) ? 1 : 0;
            else              v = (m[i] != 0) ? 1 : 0;
            g_maskb[i] = v;
        }
    } else if (bid <= NROWS) {
        // ---- split x ----
        int idx = (bid - 1) * 256 + threadIdx.x;
        float2 v = ((const float2*)x)[idx];
        unsigned hp = pack_bf16(v.y, v.x);
        float b0 = __uint_as_float(hp << 16);
        float b1 = __uint_as_float(hp & 0xFFFF0000u);
        unsigned lp = pack_bf16(v.y - b1, v.x - b0);
        g_xh[idx] = hp;
        g_xl[idx] = lp;
    } else {
        // ---- split weights ----
        int idx = (bid - NROWS - 1) * 256 + threadIdx.x;
        const int total1 = (DIN / 2) * QKV_COLS;             // 393216
        float a, b;
        unsigned* dh;
        unsigned* dl;
        int off;
        if (idx < total1) {
            int kp = idx / QKV_COLS, n = idx % QKV_COLS;
            if (n < 512) {
                a = Wq[(2 * kp) * 512 + n] * SCALE;
                b = Wq[(2 * kp + 1) * 512 + n] * SCALE;
            } else {
                int nn = n - 512;
                a = Wkv[(2 * kp) * 1024 + nn];
                b = Wkv[(2 * kp + 1) * 1024 + nn];
            }
            dh = g_wqkvh; dl = g_wqkvl; off = idx;
        } else {
            int j = idx - total1;
            int kp = j / DOUT, n = j % DOUT;
            a = Wout[(2 * kp) * DOUT + n];
            b = Wout[(2 * kp + 1) * DOUT + n];
            dh = g_wouth; dl = g_woutl; off = j;
        }
        unsigned hp = pack_bf16(b, a);
        float a0 = __uint_as_float(hp << 16);
        float b0 = __uint_as_float(hp & 0xFFFF0000u);
        unsigned lp = pack_bf16(b - b0, a - a0);
        dh[off] = hp;
        dl[off] = lp;
    }
}

// =====================================================================
// k_mid: fused  [CTA 0..1535]     QKV GEMM (tensor-bound)
//               [CTA 1536..9727]  bias transpose+mask (DRAM-bound)
// The two parts are independent; co-residency overlaps DRAM with tensor.
// GEMM: bf16 hi/lo 3-mma (m16n8k16), tile 128x64, 2-stage cp.async.
//   g_qkv = x @ [SCALE*Wq|Wkv], epilogue tf32-rounds output.
// Transpose: bias_t[b,h,i,j] = mask[b,j] ? sim_bias[b,i,j,h] : -1e30
// =====================================================================
#define GAS 20   // u32 row stride A smem
#define GBS 72   // u32 row stride B smem
#define GEMM_SMEM ((2*128*GAS*2 + 2*16*GBS*2) * 4)   // 59392 bytes
#define N_GEMM_CTAS ((QKV_COLS/64) * (NROWS/128))    // 1536
__global__ __launch_bounds__(256, 2) void k_mid(const float* __restrict__ bias) {
    extern __shared__ unsigned smg[];
    const int bid = blockIdx.x;
    const int tid = threadIdx.x;

    if (bid < N_GEMM_CTAS) {
        // ================= QKV GEMM =================
        unsigned* sAh = smg;
        unsigned* sAl = sAh + 2 * 128 * GAS;
        unsigned* sBh = sAl + 2 * 128 * GAS;
        unsigned* sBl = sBh + 2 * 16 * GBS;

        const int lane = tid & 31, warp = tid >> 5;
        const int g = lane >> 2, t = lane & 3;
        const int cb = (bid % (QKV_COLS / 64)) * 64;
        const int rb = (bid / (QKV_COLS / 64)) * 128;
        const int m0 = warp * 16;

        const int ar0 = tid >> 2, ac4 = (tid & 3) * 4;
        const int br = tid >> 4, bc4 = (tid & 15) * 4;

        auto load_stage = [&](int st, int kt) {
            const int kp0 = kt * 16;
            unsigned* pAh = sAh + st * 128 * GAS;
            unsigned* pAl = sAl + st * 128 * GAS;
            #pragma unroll
            for (int sIt = 0; sIt < 2; sIt++) {
                int r = ar0 + sIt * 64;
                size_t go = (size_t)(rb + r) * 256 + kp0 + ac4;
                cp16(&pAh[r * GAS + ac4], g_xh + go);
                cp16(&pAl[r * GAS + ac4], g_xl + go);
            }
            size_t go = (size_t)(kp0 + br) * QKV_COLS + cb + bc4;
            cp16(&sBh[st * 16 * GBS + br * GBS + bc4], g_wqkvh + go);
            cp16(&sBl[st * 16 * GBS + br * GBS + bc4], g_wqkvl + go);
        };

        float acc[8][4];
        #pragma unroll
        for (int i = 0; i < 8; i++)
            #pragma unroll
            for (int j = 0; j < 4; j++) acc[i][j] = 0.f;

        load_stage(0, 0);
        CP_COMMIT;

        for (int kt = 0; kt < 16; kt++) {
            CP_WAIT0;
            __syncthreads();
            if (kt < 15) { load_stage((kt + 1) & 1, kt + 1); CP_COMMIT; }

            const unsigned* pAh = sAh + (kt & 1) * 128 * GAS;
            const unsigned* pAl = sAl + (kt & 1) * 128 * GAS;
            const unsigned* pBh = sBh + (kt & 1) * 16 * GBS;
            const unsigned* pBl = sBl + (kt & 1) * 16 * GBS;

            #pragma unroll
            for (int kc = 0; kc < 2; kc++) {
                const int ko = kc * 8;
                unsigned ah0 = pAh[(m0 + g) * GAS + ko + t];
                unsigned ah1 = pAh[(m0 + g + 8) * GAS + ko + t];
                unsigned ah2 = pAh[(m0 + g) * GAS + ko + t + 4];
                unsigned ah3 = pAh[(m0 + g + 8) * GAS + ko + t + 4];
                unsigned al0 = pAl[(m0 + g) * GAS + ko + t];
                unsigned al1 = pAl[(m0 + g + 8) * GAS + ko + t];
                unsigned al2 = pAl[(m0 + g) * GAS + ko + t + 4];
                unsigned al3 = pAl[(m0 + g + 8) * GAS + ko + t + 4];
                #pragma unroll
                for (int nb = 0; nb < 8; nb++) {
                    unsigned bh0 = pBh[(ko + t) * GBS + nb * 8 + g];
                    unsigned bh1 = pBh[(ko + t + 4) * GBS + nb * 8 + g];
                    unsigned bl0 = pBl[(ko + t) * GBS + nb * 8 + g];
                    unsigned bl1 = pBl[(ko + t + 4) * GBS + nb * 8 + g];
                    mma16bf(acc[nb][0], acc[nb][1], acc[nb][2], acc[nb][3], ah0, ah1, ah2, ah3, bh0, bh1);
                    mma16bf(acc[nb][0], acc[nb][1], acc[nb][2], acc[nb][3], ah0, ah1, ah2, ah3, bl0, bl1);
                    mma16bf(acc[nb][0], acc[nb][1], acc[nb][2], acc[nb][3], al0, al1, al2, al3, bh0, bh1);
                }
            }
            __syncthreads();
        }

        #pragma unroll
        for (int nb = 0; nb < 8; nb++) {
            int col = cb + nb * 8 + 2 * t;
            int r0 = rb + m0 + g;
            int r1 = r0 + 8;
            *(float2*)(g_qkv + (size_t)r0 * QKV_COLS + col) =
                make_float2(to_tf32(acc[nb][0]), to_tf32(acc[nb][1]));
            *(float2*)(g_qkv + (size_t)r1 * QKV_COLS + col) =
                make_float2(to_tf32(acc[nb][2]), to_tf32(acc[nb][3]));
        }
    } else {
        // ================= bias transpose + mask =================
        float* s = (float*)smg;                                // NN*9 floats = 36864B
        unsigned char* ms = (unsigned char*)smg + NN * 9 * 4;  // 1024B
        const int bi = bid - N_GEMM_CTAS;
        const int b = bi >> 10;
        const float* src = bias + (size_t)bi * (NN * HH);

        #pragma unroll
        for (int sIt = 0; sIt < 8; sIt++) {
            int idx = tid + sIt * 256;
            float4 v = *(const float4*)(src + idx * 4);
            int j = idx >> 1;
            int h = (idx & 1) * 4;
            s[j * 9 + h + 0] = v.x;
            s[j * 9 + h + 1] = v.y;
            s[j * 9 + h + 2] = v.z;
            s[j * 9 + h + 3] = v.w;
        }
        for (int j = tid; j < NN; j += 256) ms[j] = g_maskb[b * NN + j];
        __syncthreads();

        const int i = bi & (NN - 1);
        // scalar scheme: j = tid + r*256 -> smem bank (9*lane+h)%32, 9 odd => conflict-free;
        // stores coalesced (consecutive j within warp).
        #pragma unroll
        for (int h = 0; h < HH; h++) {
            float* dst = g_bias_t + (((size_t)(b * HH + h)) * NN + i) * NN;
            #pragma unroll
            for (int r = 0; r < 4; r++) {
                int j = tid + r * 256;
                dst[j] = ms[j] ? s[j * 9 + h] : -1e30f;
            }
        }
    }
}

// =====================================================================
// out-proj GEMM: out = att @ Wout + bout  (same scheme as QKV GEMM)
// =====================================================================
__global__ __launch_bounds__(256, 2) void k_gemm_out(const float* __restrict__ bout,
                                                     float* __restrict__ Cout) {
    extern __shared__ unsigned smg[];
    unsigned* sAh = smg;
    unsigned* sAl = sAh + 2 * 128 * GAS;
    unsigned* sBh = sAl + 2 * 128 * GAS;
    unsigned* sBl = sBh + 2 * 16 * GBS;

    const int tid = threadIdx.x, lane = tid & 31, warp = tid >> 5;
    const int g = lane >> 2, t = lane & 3;
    const int cb = blockIdx.x * 64;
    const int rb = blockIdx.y * 128;
    const int m0 = warp * 16;

    const int ar0 = tid >> 2, ac4 = (tid & 3) * 4;
    const int br = tid >> 4, bc4 = (tid & 15) * 4;

    auto load_stage = [&](int st, int kt) {
        const int kp0 = kt * 16;
        unsigned* pAh = sAh + st * 128 * GAS;
        unsigned* pAl = sAl + st * 128 * GAS;
        #pragma unroll
        for (int sIt = 0; sIt < 2; sIt++) {
            int r = ar0 + sIt * 64;
            size_t go = (size_t)(rb + r) * 256 + kp0 + ac4;
            cp16(&pAh[r * GAS + ac4], g_atth + go);
            cp16(&pAl[r * GAS + ac4], g_attl + go);
        }
        size_t go = (size_t)(kp0 + br) * DOUT + cb + bc4;
        cp16(&sBh[st * 16 * GBS + br * GBS + bc4], g_wouth + go);
        cp16(&sBl[st * 16 * GBS + br * GBS + bc4], g_woutl + go);
    };

    float acc[8][4];
    #pragma unroll
    for (int i = 0; i < 8; i++)
        #pragma unroll
        for (int j = 0; j < 4; j++) acc[i][j] = 0.f;

    load_stage(0, 0);
    CP_COMMIT;

    for (int kt = 0; kt < 16; kt++) {
        CP_WAIT0;
        __syncthreads();
        if (kt < 15) { load_stage((kt + 1) & 1, kt + 1); CP_COMMIT; }

        const unsigned* pAh = sAh + (kt & 1) * 128 * GAS;
        const unsigned* pAl = sAl + (kt & 1) * 128 * GAS;
        const unsigned* pBh = sBh + (kt & 1) * 16 * GBS;
        const unsigned* pBl = sBl + (kt & 1) * 16 * GBS;

        #pragma unroll
        for (int kc = 0; kc < 2; kc++) {
            const int ko = kc * 8;
            unsigned ah0 = pAh[(m0 + g) * GAS + ko + t];
            unsigned ah1 = pAh[(m0 + g + 8) * GAS + ko + t];
            unsigned ah2 = pAh[(m0 + g) * GAS + ko + t + 4];
            unsigned ah3 = pAh[(m0 + g + 8) * GAS + ko + t + 4];
            unsigned al0 = pAl[(m0 + g) * GAS + ko + t];
            unsigned al1 = pAl[(m0 + g + 8) * GAS + ko + t];
            unsigned al2 = pAl[(m0 + g) * GAS + ko + t + 4];
            unsigned al3 = pAl[(m0 + g + 8) * GAS + ko + t + 4];
            #pragma unroll
            for (int nb = 0; nb < 8; nb++) {
                unsigned bh0 = pBh[(ko + t) * GBS + nb * 8 + g];
                unsigned bh1 = pBh[(ko + t + 4) * GBS + nb * 8 + g];
                unsigned bl0 = pBl[(ko + t) * GBS + nb * 8 + g];
                unsigned bl1 = pBl[(ko + t + 4) * GBS + nb * 8 + g];
                mma16bf(acc[nb][0], acc[nb][1], acc[nb][2], acc[nb][3], ah0, ah1, ah2, ah3, bh0, bh1);
                mma16bf(acc[nb][0], acc[nb][1], acc[nb][2], acc[nb][3], ah0, ah1, ah2, ah3, bl0, bl1);
                mma16bf(acc[nb][0], acc[nb][1], acc[nb][2], acc[nb][3], al0, al1, al2, al3, bh0, bh1);
            }
        }
        __syncthreads();
    }

    #pragma unroll
    for (int nb = 0; nb < 8; nb++) {
        int col = cb + nb * 8 + 2 * t;
        float b0v = bout[col], b1v = bout[col + 1];
        int r0 = rb + m0 + g;
        int r1 = r0 + 8;
        *(float2*)(Cout + (size_t)r0 * DOUT + col) = make_float2(acc[nb][0] + b0v, acc[nb][1] + b1v);
        *(float2*)(Cout + (size_t)r1 * DOUT + col) = make_float2(acc[nb][2] + b0v, acc[nb][3] + b1v);
    }
}

// =====================================================================
// Flash attention. CTA = (b,h,i-tile 128). 256 thr / 8 warps.
// K/V committed as group A, bias as group B: bias arrival hides behind QK^T.
// f32 bias overlays the P buffer; per-warp rows, so P overwrite needs only
// __syncwarp after the cross-thread bias visibility barrier.
// =====================================================================
#define FS 68
__global__ __launch_bounds__(256, 2) void k_flash() {
    extern __shared__ float sm[];
    float* Qs = sm;                       // 128*FS
    float* Ks = Qs + 128 * FS;            // 64*FS
    float* Vs = Ks + 64 * FS;             // 64*FS
    float* Ps = Vs + 64 * FS;             // 128*FS  (bias f32 overlay + P)

    const int tid = threadIdx.x, lane = tid & 31, warp = tid >> 5;
    const int g = lane >> 2, t = lane & 3;
    const int it = blockIdx.x & 7;
    const int bh = blockIdx.x >> 3;
    const int b = bh >> 3, h = bh & 7;
    const int i0 = it * 128;
    const int m0 = warp * 16;
    const float NEG_INF = __int_as_float(0xff800000);

    const float* qbase = g_qkv + (size_t)b * NN * QKV_COLS;
    const float* bbase = g_bias_t + ((size_t)bh * NN + i0) * NN;

    // Q tile via cp.async
    {
        int r = tid >> 4, c4 = (tid & 15) * 4;
        #pragma unroll
        for (int sIt = 0; sIt < 8; sIt++) {
            cp16(&Qs[(r + sIt * 16) * FS + c4],
                 qbase + (size_t)(i0 + r + sIt * 16) * QKV_COLS + h * 64 + c4);
        }
    }
    CP_COMMIT;

    float accO[8][4];
    #pragma unroll
    for (int i = 0; i < 8; i++)
        #pragma unroll
        for (int j = 0; j < 4; j++) accO[i][j] = 0.f;
    float mrow0 = NEG_INF, mrow1 = NEG_INF;
    float lrow0 = 0.f, lrow1 = 0.f;

    const int kvr = tid >> 4, kvc4 = (tid & 15) * 4;

    for (int jt = 0; jt < 16; jt++) {
        const int j0 = jt * 64;
        __syncthreads();                                   // Ps/Ks/Vs free
        #pragma unroll
        for (int sIt = 0; sIt < 4; sIt++) {
            int r = kvr + sIt * 16;
            const float* kp = qbase + (size_t)(j0 + r) * QKV_COLS + 512 + h * 64 + kvc4;
            cp16(&Ks[r * FS + kvc4], kp);
            cp16(&Vs[r * FS + kvc4], kp + 512);
        }
        CP_COMMIT;                                         // group A: K/V
        #pragma unroll
        for (int sIt = 0; sIt < 8; sIt++) {
            int r = kvr + sIt * 16;
            cp16(&Ps[r * FS + kvc4], bbase + (size_t)r * NN + j0 + kvc4);
        }
        CP_COMMIT;                                         // group B: bias
        CP_WAIT1;                                          // K/V landed (bias may be in flight)
        __syncthreads();

        // S = Q @ K^T  (bias group B streams in under this)
        float s[8][4];
        #pragma unroll
        for (int i = 0; i < 8; i++)
            #pragma unroll
            for (int j = 0; j < 4; j++) s[i][j] = 0.f;
        #pragma unroll
        for (int ks = 0; ks < 8; ks++) {
            const int kk = ks * 8;
            unsigned a0 = __float_as_uint(Qs[(m0 + g) * FS + kk + t]);
            unsigned a1 = __float_as_uint(Qs[(m0 + g + 8) * FS + kk + t]);
            unsigned a2 = __float_as_uint(Qs[(m0 + g) * FS + kk + t + 4]);
            unsigned a3 = __float_as_uint(Qs[(m0 + g + 8) * FS + kk + t + 4]);
            #pragma unroll
            for (int nb = 0; nb < 8; nb++) {
                unsigned b0 = __float_as_uint(Ks[(nb * 8 + g) * FS + kk + t]);
                unsigned b1 = __float_as_uint(Ks[(nb * 8 + g) * FS + kk + t + 4]);
                mma8(s[nb][0], s[nb][1], s[nb][2], s[nb][3], a0, a1, a2, a3, b0, b1);
            }
        }
        CP_WAIT0;                                          // this thread's bias done
        __syncthreads();                                   // all threads' bias visible

        // + bias (f32, includes -1e30 mask), row max
        float mx0 = NEG_INF, mx1 = NEG_INF;
        #pragma unroll
        for (int nb = 0; nb < 8; nb++) {
            int c = nb * 8 + 2 * t;
            float2 bA = *(float2*)&Ps[(m0 + g) * FS + c];
            float2 bB = *(float2*)&Ps[(m0 + g + 8) * FS + c];
            s[nb][0] += bA.x;
            s[nb][1] += bA.y;
            s[nb][2] += bB.x;
            s[nb][3] += bB.y;
            mx0 = fmaxf(mx0, fmaxf(s[nb][0], s[nb][1]));
            mx1 = fmaxf(mx1, fmaxf(s[nb][2], s[nb][3]));
        }
        mx0 = fmaxf(mx0, __shfl_xor_sync(0xffffffffu, mx0, 1));
        mx0 = fmaxf(mx0, __shfl_xor_sync(0xffffffffu, mx0, 2));
        mx1 = fmaxf(mx1, __shfl_xor_sync(0xffffffffu, mx1, 1));
        mx1 = fmaxf(mx1, __shfl_xor_sync(0xffffffffu, mx1, 2));

        float mn0 = fmaxf(mrow0, mx0), mn1 = fmaxf(mrow1, mx1);
        float al0 = ex2((mrow0 - mn0) * LOG2E);
        float al1 = ex2((mrow1 - mn1) * LOG2E);
        mrow0 = mn0;
        mrow1 = mn1;

        float sum0 = 0.f, sum1 = 0.f;
        #pragma unroll
        for (int nb = 0; nb < 8; nb++) {
            float p0 = ex2((s[nb][0] - mn0) * LOG2E);
            float p1 = ex2((s[nb][1] - mn0) * LOG2E);
            float p2 = ex2((s[nb][2] - mn1) * LOG2E);
            float p3 = ex2((s[nb][3] - mn1) * LOG2E);
            sum0 += p0 + p1;
            sum1 += p2 + p3;
            int c = nb * 8 + 2 * t;
            *(float2*)&Ps[(m0 + g) * FS + c] = make_float2(to_tf32(p0), to_tf32(p1));
            *(float2*)&Ps[(m0 + g + 8) * FS + c] = make_float2(to_tf32(p2), to_tf32(p3));
        }
        sum0 += __shfl_xor_sync(0xffffffffu, sum0, 1);
        sum0 += __shfl_xor_sync(0xffffffffu, sum0, 2);
        sum1 += __shfl_xor_sync(0xffffffffu, sum1, 1);
        sum1 += __shfl_xor_sync(0xffffffffu, sum1, 2);
        lrow0 = lrow0 * al0 + sum0;
        lrow1 = lrow1 * al1 + sum1;

        #pragma unroll
        for (int nb = 0; nb < 8; nb++) {
            accO[nb][0] *= al0;
            accO[nb][1] *= al0;
            accO[nb][2] *= al1;
            accO[nb][3] *= al1;
        }
        __syncwarp();
        // O += P @ V   (P rows warp-private)
        #pragma unroll
        for (int ks = 0; ks < 8; ks++) {
            const int kk = ks * 8;
            unsigned a0 = __float_as_uint(Ps[(m0 + g) * FS + kk + t]);
            unsigned a1 = __float_as_uint(Ps[(m0 + g + 8) * FS + kk + t]);
            unsigned a2 = __float_as_uint(Ps[(m0 + g) * FS + kk + t + 4]);
            unsigned a3 = __float_as_uint(Ps[(m0 + g + 8) * FS + kk + t + 4]);
            #pragma unroll
            for (int nb = 0; nb < 8; nb++) {
                unsigned b0 = __float_as_uint(Vs[(kk + t) * FS + nb * 8 + g]);
                unsigned b1 = __float_as_uint(Vs[(kk + t + 4) * FS + nb * 8 + g]);
                mma8(accO[nb][0], accO[nb][1], accO[nb][2], accO[nb][3], a0, a1, a2, a3, b0, b1);
            }
        }
    }

    // epilogue: normalize, split to bf16 hi/lo pairs
    float inv0 = 1.f / lrow0;
    float inv1 = 1.f / lrow1;
    #pragma unroll
    for (int nb = 0; nb < 8; nb++) {
        int cp = h * 32 + nb * 4 + t;
        int r0 = b * NN + i0 + m0 + g;
        int r1 = r0 + 8;
        {
            float o0 = accO[nb][0] * inv0, o1 = accO[nb][1] * inv0;
            unsigned hp = pack_bf16(o1, o0);
            float c0 = __uint_as_float(hp << 16);
            float c1 = __uint_as_float(hp & 0xFFFF0000u);
            unsigned lp = pack_bf16(o1 - c1, o0 - c0);
            g_atth[(size_t)r0 * 256 + cp] = hp;
            g_attl[(size_t)r0 * 256 + cp] = lp;
        }
        {
            float o0 = accO[nb][2] * inv1, o1 = accO[nb][3] * inv1;
            unsigned hp = pack_bf16(o1, o0);
            float c0 = __uint_as_float(hp << 16);
            float c1 = __uint_as_float(hp & 0xFFFF0000u);
            unsigned lp = pack_bf16(o1 - c1, o0 - c0);
            g_atth[(size_t)r1 * 256 + cp] = hp;
            g_attl[(size_t)r1 * 256 + cp] = lp;
        }
    }
}

// =====================================================================
extern "C" void kernel_launch(void* const* d_in, const int* in_sizes, int n_in,
                              void* d_out, int out_size) {
    (void)in_sizes; (void)n_in; (void)out_size;
    const float* x = (const float*)d_in[0];
    const unsigned char* mask = (const unsigned char*)d_in[1];
    const float* bias = (const float*)d_in[2];
    const float* Wq = (const float*)d_in[3];
    const float* Wkv = (const float*)d_in[4];
    const float* Wout = (const float*)d_in[5];
    const float* bout = (const float*)d_in[6];
    float* out = (float*)d_out;

    const int flash_smem = (128 + 64 + 64 + 128) * FS * 4;   // 104448
    cudaFuncSetAttribute(k_flash, cudaFuncAttributeMaxDynamicSharedMemorySize, flash_smem);
    cudaFuncSetAttribute(k_mid, cudaFuncAttributeMaxDynamicSharedMemorySize, GEMM_SMEM);
    cudaFuncSetAttribute(k_gemm_out, cudaFuncAttributeMaxDynamicSharedMemorySize, GEMM_SMEM);

    // prep: mask(1) + split_x(8192) + split_w(2048)
    k_prep<<<1 + NROWS + 2048, 256>>>(mask, x, Wq, Wkv, Wout);
    // mid: QKV GEMM (1536, tensor) + bias transpose (8192, DRAM) overlapped
    k_mid<<<N_GEMM_CTAS + BB * NN, 256, GEMM_SMEM>>>(bias);
    k_flash<<<BB * HH * (NN / 128), 256, flash_smem>>>();
    k_gemm_out<<<dim3(DOUT / 64, NROWS / 128), 256, GEMM_SMEM>>>(bout, out);
}

// round 7
// speedup vs baseline: 2.1690x; 1.1240x over previous
#include <cuda_runtime.h>
#include <cuda_bf16.h>

#define BB 8
#define NN 1024
#define DIN 512
#define HH 8
#define INNER 512
#define DOUT 512
#define NROWS (BB*NN)            // 8192
#define QKV_COLS 1536
#define SCALE 0.125f
#define LOG2E 1.4426950408889634f

// ---- scratch (device globals; no runtime allocation) ----
__device__ float g_qkv[(size_t)NROWS * QKV_COLS];           // q|k (tf32-rounded); V region unused
__device__ float g_vT[(size_t)BB * HH * 64 * NN];           // V^T per (b,h): [d][token], tf32, 16MB
__device__ float g_bias_t[(size_t)BB * HH * NN * NN];       // bias transposed+masked f32, 256MB
__device__ unsigned g_xh[(size_t)NROWS * (DIN/2)];          // x hi bf16 pairs [row][kp]
__device__ unsigned g_xl[(size_t)NROWS * (DIN/2)];
__device__ unsigned g_wqkvh[(size_t)QKV_COLS * 256];        // [SCALE*Wq|Wkv] n-major [n][kp]
__device__ unsigned g_wqkvl[(size_t)QKV_COLS * 256];
__device__ unsigned g_wouth[(size_t)DOUT * 256];            // Wout n-major [n][kp]
__device__ unsigned g_woutl[(size_t)DOUT * 256];
__device__ unsigned g_atth[(size_t)NROWS * (INNER/2)];      // attention out hi pairs [row][kp]
__device__ unsigned g_attl[(size_t)NROWS * (INNER/2)];
__device__ unsigned char g_maskb[BB * NN];

// ---- helpers ----
__device__ __forceinline__ float to_tf32(float x) {
    unsigned u;
    asm("cvt.rna.tf32.f32 %0, %1;" : "=r"(u) : "f"(x));
    return __uint_as_float(u);
}
__device__ __forceinline__ float ex2(float x) {
    float y;
    asm("ex2.approx.ftz.f32 %0, %1;" : "=f"(y) : "f"(x));
    return y;
}
__device__ __forceinline__ unsigned pack_bf16(float hi_elem, float lo_elem) {
    unsigned r;
    asm("cvt.rn.bf16x2.f32 %0, %1, %2;" : "=r"(r) : "f"(hi_elem), "f"(lo_elem));
    return r;
}
__device__ __forceinline__ void cp16(void* sp, const void* gp) {
    unsigned s = (unsigned)__cvta_generic_to_shared(sp);
    asm volatile("cp.async.cg.shared.global [%0], [%1], 16;\n" :: "r"(s), "l"(gp));
}
#define CP_COMMIT asm volatile("cp.async.commit_group;\n")
#define CP_WAIT0  asm volatile("cp.async.wait_group 0;\n")
#define CP_WAIT1  asm volatile("cp.async.wait_group 1;\n")

// ldmatrix x4: reg j <- matrix from address-lane-group j; thread receives
// (row = lane/4, u32col = lane%4) of each matrix. Bit-preserving for tf32/bf16x2.
__device__ __forceinline__ void ldsm4(unsigned& r0, unsigned& r1, unsigned& r2, unsigned& r3,
                                      unsigned saddr) {
    asm volatile("ldmatrix.sync.aligned.m8n8.x4.shared.b16 {%0,%1,%2,%3}, [%4];"
                 : "=r"(r0), "=r"(r1), "=r"(r2), "=r"(r3) : "r"(saddr));
}
__device__ __forceinline__ void mma8(float& c0, float& c1, float& c2, float& c3,
                                     unsigned a0, unsigned a1, unsigned a2, unsigned a3,
                                     unsigned b0, unsigned b1) {
    asm volatile(
        "mma.sync.aligned.m16n8k8.row.col.f32.tf32.tf32.f32 "
        "{%0,%1,%2,%3},{%4,%5,%6,%7},{%8,%9},{%0,%1,%2,%3};\n"
        : "+f"(c0), "+f"(c1), "+f"(c2), "+f"(c3)
        : "r"(a0), "r"(a1), "r"(a2), "r"(a3), "r"(b0), "r"(b1));
}
__device__ __forceinline__ void mma16bf(float& c0, float& c1, float& c2, float& c3,
                                        unsigned a0, unsigned a1, unsigned a2, unsigned a3,
                                        unsigned b0, unsigned b1) {
    asm volatile(
        "mma.sync.aligned.m16n8k16.row.col.f32.bf16.bf16.f32 "
        "{%0,%1,%2,%3},{%4,%5,%6,%7},{%8,%9},{%0,%1,%2,%3};\n"
        : "+f"(c0), "+f"(c1), "+f"(c2), "+f"(c3)
        : "r"(a0), "r"(a1), "r"(a2), "r"(a3), "r"(b0), "r"(b1));
}

// =====================================================================
// k_prep: [CTA 0] mask expand; [1..8192] split x; [8193..10240] split W
// Weights written n-major: gW[n*256 + kp].
// =====================================================================
__global__ __launch_bounds__(256) void k_prep(const unsigned char* __restrict__ m,
                                              const float* __restrict__ x,
                                              const float* __restrict__ Wq,
                                              const float* __restrict__ Wkv,
                                              const float* __restrict__ Wout) {
    const int bid = blockIdx.x;
    if (bid == 0) {
        __shared__ int s_notI32, s_notF32;
        if (threadIdx.x == 0) { s_notI32 = 0; s_notF32 = 0; }
        __syncthreads();
        const unsigned* mw = (const unsigned*)m;
        int notI = 0, notF = 0;
        for (int i = threadIdx.x; i < BB * NN / 4; i += 256) {
            unsigned w = mw[i];
            if (w & 0xFFFFFF00u) notI = 1;
            if (w != 0u && w != 0x3F800000u) notF = 1;
        }
        if (notI) atomicOr(&s_notI32, 1);
        if (notF) atomicOr(&s_notF32, 1);
        __syncthreads();
        const int notI32 = s_notI32, notF32 = s_notF32;
        for (int i = threadIdx.x; i < BB * NN; i += 256) {
            unsigned char v;
            if (!notF32)      v = (((const unsigned*)m)[i] != 0u) ? 1 : 0;
            else if (!notI32) v = (((const int*)m)[i] != 0) ? 1 : 0;
            else              v = (m[i] != 0) ? 1 : 0;
            g_maskb[i] = v;
        }
    } else if (bid <= NROWS) {
        int idx = (bid - 1) * 256 + threadIdx.x;
        float2 v = ((const float2*)x)[idx];
        unsigned hp = pack_bf16(v.y, v.x);
        float b0 = __uint_as_float(hp << 16);
        float b1 = __uint_as_float(hp & 0xFFFF0000u);
        unsigned lp = pack_bf16(v.y - b1, v.x - b0);
        g_xh[idx] = hp;
        g_xl[idx] = lp;
    } else {
        int idx = (bid - NROWS - 1) * 256 + threadIdx.x;
        const int total1 = 256 * QKV_COLS;               // (kp,n) pairs for qkv
        float a, b;
        unsigned* dh;
        unsigned* dl;
        size_t off;
        if (idx < total1) {
            int kp = idx / QKV_COLS, n = idx % QKV_COLS;   // reads coalesced over n
            if (n < 512) {
                a = Wq[(2 * kp) * 512 + n] * SCALE;
                b = Wq[(2 * kp + 1) * 512 + n] * SCALE;
            } else {
                int nn = n - 512;
                a = Wkv[(2 * kp) * 1024 + nn];
                b = Wkv[(2 * kp + 1) * 1024 + nn];
            }
            dh = g_wqkvh; dl = g_wqkvl;
            off = (size_t)n * 256 + kp;                    // n-major write
        } else {
            int j = idx - total1;
            int kp = j / DOUT, n = j % DOUT;
            a = Wout[(2 * kp) * DOUT + n];
            b = Wout[(2 * kp + 1) * DOUT + n];
            dh = g_wouth; dl = g_woutl;
            off = (size_t)n * 256 + kp;
        }
        unsigned hp = pack_bf16(b, a);
        float a0 = __uint_as_float(hp << 16);
        float b0 = __uint_as_float(hp & 0xFFFF0000u);
        unsigned lp = pack_bf16(b - b0, a - a0);
        dh[off] = hp;
        dl[off] = lp;
    }
}

// =====================================================================
// Shared GEMM core (bf16 hi/lo 3-mma, tile 128x64, 2-stage cp.async, LDSM).
// A: [row][kp] packed u32. B: n-major [n][kp] packed u32.
// =====================================================================
#define GAS 20   // u32 row stride A smem (80B = 5x16B, ldmatrix-aligned, conflict-free)
#define BS2 20   // u32 row stride B smem
#define GEMM_SMEM ((2*128*GAS*2 + 2*64*BS2*2) * 4)   // 61440 bytes
#define N_GEMM_CTAS ((QKV_COLS/64) * (NROWS/128))    // 1536

template <int MODE>   // 0 = QKV (epilogue: tf32 q/k + V^T scatter), 1 = out-proj
__device__ __forceinline__ void gemm_core(unsigned* smg, int cbid,
                                          const unsigned* __restrict__ Agh,
                                          const unsigned* __restrict__ Agl,
                                          const unsigned* __restrict__ Bgh,
                                          const unsigned* __restrict__ Bgl,
                                          const float* __restrict__ bout,
                                          float* __restrict__ Cout) {
    unsigned* sAh = smg;
    unsigned* sAl = sAh + 2 * 128 * GAS;
    unsigned* sBh = sAl + 2 * 128 * GAS;
    unsigned* sBl = sBh + 2 * 64 * BS2;

    const int tid = threadIdx.x, lane = tid & 31, warp = tid >> 5;
    const int g = lane >> 2, t = lane & 3;
    const int ncb = (MODE == 0) ? (QKV_COLS / 64) : (DOUT / 64);
    const int cb = (cbid % ncb) * 64;
    const int rb = (cbid / ncb) * 128;
    const int m0 = warp * 16;

    const int ar0 = tid >> 2, ac4 = (tid & 3) * 4;
    const int brB = tid >> 2, bc4 = (tid & 3) * 4;

    auto load_stage = [&](int st, int kt) {
        const int kp0 = kt * 16;
        unsigned* pAh = sAh + st * 128 * GAS;
        unsigned* pAl = sAl + st * 128 * GAS;
        #pragma unroll
        for (int sIt = 0; sIt < 2; sIt++) {
            int r = ar0 + sIt * 64;
            size_t go = (size_t)(rb + r) * 256 + kp0 + ac4;
            cp16(&pAh[r * GAS + ac4], Agh + go);
            cp16(&pAl[r * GAS + ac4], Agl + go);
        }
        size_t go = (size_t)(cb + brB) * 256 + kp0 + bc4;
        cp16(&sBh[st * 64 * BS2 + brB * BS2 + bc4], Bgh + go);
        cp16(&sBl[st * 64 * BS2 + brB * BS2 + bc4], Bgl + go);
    };

    // ldmatrix per-thread byte offsets
    const unsigned aoff = ((unsigned)((m0 + (lane & 15)) * GAS + ((lane & 16) >> 2))) * 4;
    const unsigned boff = ((unsigned)(((lane & 7) + ((lane & 16) >> 1)) * BS2 + ((lane & 8) >> 1))) * 4;
    const unsigned sAh_b = (unsigned)__cvta_generic_to_shared(sAh);
    const unsigned sAl_b = (unsigned)__cvta_generic_to_shared(sAl);
    const unsigned sBh_b = (unsigned)__cvta_generic_to_shared(sBh);
    const unsigned sBl_b = (unsigned)__cvta_generic_to_shared(sBl);

    float acc[8][4];
    #pragma unroll
    for (int i = 0; i < 8; i++)
        #pragma unroll
        for (int j = 0; j < 4; j++) acc[i][j] = 0.f;

    load_stage(0, 0);
    CP_COMMIT;

    for (int kt = 0; kt < 16; kt++) {
        CP_WAIT0;
        __syncthreads();
        if (kt < 15) { load_stage((kt + 1) & 1, kt + 1); CP_COMMIT; }

        const unsigned stA = (kt & 1) * 128 * GAS * 4;
        const unsigned stB = (kt & 1) * 64 * BS2 * 4;

        #pragma unroll
        for (int kc = 0; kc < 2; kc++) {
            const unsigned ko = kc * 8 * 4;   // bytes
            unsigned ah0, ah1, ah2, ah3, al0, al1, al2, al3;
            ldsm4(ah0, ah1, ah2, ah3, sAh_b + stA + aoff + ko);
            ldsm4(al0, al1, al2, al3, sAl_b + stA + aoff + ko);
            #pragma unroll
            for (int nbp = 0; nbp < 4; nbp++) {
                const unsigned bo = boff + (unsigned)(nbp * 16 * BS2) * 4 + ko;
                unsigned bh0, bh1, bh2, bh3, bl0, bl1, bl2, bl3;
                ldsm4(bh0, bh1, bh2, bh3, sBh_b + stB + bo);
                ldsm4(bl0, bl1, bl2, bl3, sBl_b + stB + bo);
                float* A0 = acc[2 * nbp];
                float* A1 = acc[2 * nbp + 1];
                mma16bf(A0[0], A0[1], A0[2], A0[3], ah0, ah1, ah2, ah3, bh0, bh1);
                mma16bf(A0[0], A0[1], A0[2], A0[3], ah0, ah1, ah2, ah3, bl0, bl1);
                mma16bf(A0[0], A0[1], A0[2], A0[3], al0, al1, al2, al3, bh0, bh1);
                mma16bf(A1[0], A1[1], A1[2], A1[3], ah0, ah1, ah2, ah3, bh2, bh3);
                mma16bf(A1[0], A1[1], A1[2], A1[3], ah0, ah1, ah2, ah3, bl2, bl3);
                mma16bf(A1[0], A1[1], A1[2], A1[3], al0, al1, al2, al3, bh2, bh3);
            }
        }
        __syncthreads();
    }

    if (MODE == 0) {
        if (cb < 1024) {
            // Q/K columns -> g_qkv (tf32-rounded)
            #pragma unroll
            for (int nb = 0; nb < 8; nb++) {
                int col = cb + nb * 8 + 2 * t;
                int r0 = rb + m0 + g;
                int r1 = r0 + 8;
                *(float2*)(g_qkv + (size_t)r0 * QKV_COLS + col) =
                    make_float2(to_tf32(acc[nb][0]), to_tf32(acc[nb][1]));
                *(float2*)(g_qkv + (size_t)r1 * QKV_COLS + col) =
                    make_float2(to_tf32(acc[nb][2]), to_tf32(acc[nb][3]));
            }
        } else {
            // V columns -> g_vT[bh][d][token] (tf32-rounded)
            int h = (cb - 1024) >> 6;
            int r0 = rb + m0 + g;
            int b = r0 >> 10, n = r0 & 1023;
            float* vt = g_vT + (size_t)(b * 8 + h) * 64 * NN;
            #pragma unroll
            for (int nb = 0; nb < 8; nb++) {
                int d = nb * 8 + 2 * t;
                vt[(size_t)d * NN + n] = to_tf32(acc[nb][0]);
                vt[(size_t)(d + 1) * NN + n] = to_tf32(acc[nb][1]);
                vt[(size_t)d * NN + n + 8] = to_tf32(acc[nb][2]);
                vt[(size_t)(d + 1) * NN + n + 8] = to_tf32(acc[nb][3]);
            }
        }
    } else {
        #pragma unroll
        for (int nb = 0; nb < 8; nb++) {
            int col = cb + nb * 8 + 2 * t;
            float b0v = bout[col], b1v = bout[col + 1];
            int r0 = rb + m0 + g;
            int r1 = r0 + 8;
            *(float2*)(Cout + (size_t)r0 * DOUT + col) = make_float2(acc[nb][0] + b0v, acc[nb][1] + b1v);
            *(float2*)(Cout + (size_t)r1 * DOUT + col) = make_float2(acc[nb][2] + b0v, acc[nb][3] + b1v);
        }
    }
}

// =====================================================================
// k_mid: interleaved QKV GEMM (tensor) + bias transpose (DRAM).
// 9728 = 19*512 CTAs; bid%19<3 -> GEMM (3*512=1536), else transpose (8192).
// =====================================================================
__global__ __launch_bounds__(256, 2) void k_mid(const float* __restrict__ bias) {
    extern __shared__ unsigned smg[];
    const int bid = blockIdx.x;
    const int tid = threadIdx.x;
    const int grp = bid / 19, rem = bid % 19;

    if (rem < 3) {
        gemm_core<0>(smg, grp * 3 + rem, g_xh, g_xl, g_wqkvh, g_wqkvl, nullptr, nullptr);
    } else {
        // ================= bias transpose + mask =================
        float* s = (float*)smg;
        unsigned char* ms = (unsigned char*)smg + NN * 9 * 4;
        const int bi = grp * 16 + (rem - 3);
        const int b = bi >> 10;
        const float* src = bias + (size_t)bi * (NN * HH);

        #pragma unroll
        for (int sIt = 0; sIt < 8; sIt++) {
            int idx = tid + sIt * 256;
            float4 v = *(const float4*)(src + idx * 4);
            int j = idx >> 1;
            int h = (idx & 1) * 4;
            s[j * 9 + h + 0] = v.x;
            s[j * 9 + h + 1] = v.y;
            s[j * 9 + h + 2] = v.z;
            s[j * 9 + h + 3] = v.w;
        }
        for (int j = tid; j < NN; j += 256) ms[j] = g_maskb[b * NN + j];
        __syncthreads();

        const int i = bi & (NN - 1);
        #pragma unroll
        for (int h = 0; h < HH; h++) {
            float* dst = g_bias_t + (((size_t)(b * HH + h)) * NN + i) * NN;
            #pragma unroll
            for (int r = 0; r < 4; r++) {
                int j = tid + r * 256;
                dst[j] = ms[j] ? s[j * 9 + h] : -1e30f;
            }
        }
    }
}

__global__ __launch_bounds__(256, 2) void k_gemm_out(const float* __restrict__ bout,
                                                     float* __restrict__ Cout) {
    extern __shared__ unsigned smg[];
    gemm_core<1>(smg, blockIdx.x, g_atth, g_attl, g_wouth, g_woutl, bout, Cout);
}

// =====================================================================
// Flash attention. CTA = (b,h,i-tile 128). 256 thr / 8 warps. LDSM fragments.
// K from g_qkv cols [512,1024); V^T from g_vT. Bias overlays P buffer.
// =====================================================================
#define FS 68
__global__ __launch_bounds__(256, 2) void k_flash() {
    extern __shared__ float sm[];
    float* Qs = sm;                       // 128*FS
    float* Ks = Qs + 128 * FS;            // 64*FS
    float* Vt = Ks + 64 * FS;             // 64*FS  V^T [d][j]
    float* Ps = Vt + 64 * FS;             // 128*FS (bias overlay + P)

    const int tid = threadIdx.x, lane = tid & 31, warp = tid >> 5;
    const int g = lane >> 2, t = lane & 3;
    const int it = blockIdx.x & 7;
    const int bh = blockIdx.x >> 3;
    const int b = bh >> 3, h = bh & 7;
    const int i0 = it * 128;
    const int m0 = warp * 16;
    const float NEG_INF = __int_as_float(0xff800000);

    const float* qbase = g_qkv + (size_t)b * NN * QKV_COLS;
    const float* kbase = qbase + 512 + h * 64;
    const float* vbase = g_vT + (size_t)bh * 64 * NN;
    const float* bbase = g_bias_t + ((size_t)bh * NN + i0) * NN;

    // ldmatrix byte offsets
    const unsigned aoff = ((unsigned)((m0 + (lane & 15)) * FS + ((lane & 16) >> 2))) * 4;
    const unsigned boff = ((unsigned)(((lane & 7) + ((lane & 16) >> 1)) * FS + ((lane & 8) >> 1))) * 4;
    const unsigned qs_b = (unsigned)__cvta_generic_to_shared(Qs);
    const unsigned ks_b = (unsigned)__cvta_generic_to_shared(Ks);
    const unsigned vt_b = (unsigned)__cvta_generic_to_shared(Vt);
    const unsigned ps_b = (unsigned)__cvta_generic_to_shared(Ps);

    // Q tile via cp.async
    {
        int r = tid >> 4, c4 = (tid & 15) * 4;
        #pragma unroll
        for (int sIt = 0; sIt < 8; sIt++) {
            cp16(&Qs[(r + sIt * 16) * FS + c4],
                 qbase + (size_t)(i0 + r + sIt * 16) * QKV_COLS + h * 64 + c4);
        }
    }
    CP_COMMIT;

    float accO[8][4];
    #pragma unroll
    for (int i = 0; i < 8; i++)
        #pragma unroll
        for (int j = 0; j < 4; j++) accO[i][j] = 0.f;
    float mrow0 = NEG_INF, mrow1 = NEG_INF;
    float lrow0 = 0.f, lrow1 = 0.f;

    const int kvr = tid >> 4, kvc4 = (tid & 15) * 4;

    for (int jt = 0; jt < 16; jt++) {
        const int j0 = jt * 64;
        __syncthreads();                                   // buffers free
        #pragma unroll
        for (int sIt = 0; sIt < 4; sIt++) {
            int r = kvr + sIt * 16;
            cp16(&Ks[r * FS + kvc4], kbase + (size_t)(j0 + r) * QKV_COLS + kvc4);
            cp16(&Vt[r * FS + kvc4], vbase + (size_t)r * NN + j0 + kvc4);
        }
        CP_COMMIT;                                         // group: K/V
        #pragma unroll
        for (int sIt = 0; sIt < 8; sIt++) {
            int r = kvr + sIt * 16;
            cp16(&Ps[r * FS + kvc4], bbase + (size_t)r * NN + j0 + kvc4);
        }
        CP_COMMIT;                                         // group: bias
        CP_WAIT1;                                          // K/V landed
        __syncthreads();

        // S = Q @ K^T via LDSM fragments
        float s[8][4];
        #pragma unroll
        for (int i = 0; i < 8; i++)
            #pragma unroll
            for (int j = 0; j < 4; j++) s[i][j] = 0.f;
        #pragma unroll
        for (int ks = 0; ks < 8; ks++) {
            const unsigned ko = ks * 32;                   // 8 floats = 32 bytes
            unsigned a0, a1, a2, a3;
            ldsm4(a0, a1, a2, a3, qs_b + aoff + ko);
            #pragma unroll
            for (int nbp = 0; nbp < 4; nbp++) {
                unsigned b0, b1, c0, c1;
                ldsm4(b0, b1, c0, c1, ks_b + boff + (unsigned)(nbp * 16 * FS) * 4 + ko);
                float* S0 = s[2 * nbp];
                float* S1 = s[2 * nbp + 1];
                mma8(S0[0], S0[1], S0[2], S0[3], a0, a1, a2, a3, b0, b1);
                mma8(S1[0], S1[1], S1[2], S1[3], a0, a1, a2, a3, c0, c1);
            }
        }
        CP_WAIT0;                                          // bias done
        __syncthreads();

        // + bias, row max
        float mx0 = NEG_INF, mx1 = NEG_INF;
        #pragma unroll
        for (int nb = 0; nb < 8; nb++) {
            int c = nb * 8 + 2 * t;
            float2 bA = *(float2*)&Ps[(m0 + g) * FS + c];
            float2 bB = *(float2*)&Ps[(m0 + g + 8) * FS + c];
            s[nb][0] += bA.x;
            s[nb][1] += bA.y;
            s[nb][2] += bB.x;
            s[nb][3] += bB.y;
            mx0 = fmaxf(mx0, fmaxf(s[nb][0], s[nb][1]));
            mx1 = fmaxf(mx1, fmaxf(s[nb][2], s[nb][3]));
        }
        mx0 = fmaxf(mx0, __shfl_xor_sync(0xffffffffu, mx0, 1));
        mx0 = fmaxf(mx0, __shfl_xor_sync(0xffffffffu, mx0, 2));
        mx1 = fmaxf(mx1, __shfl_xor_sync(0xffffffffu, mx1, 1));
        mx1 = fmaxf(mx1, __shfl_xor_sync(0xffffffffu, mx1, 2));

        float mn0 = fmaxf(mrow0, mx0), mn1 = fmaxf(mrow1, mx1);
        float al0 = ex2((mrow0 - mn0) * LOG2E);
        float al1 = ex2((mrow1 - mn1) * LOG2E);
        mrow0 = mn0;
        mrow1 = mn1;

        float sum0 = 0.f, sum1 = 0.f;
        #pragma unroll
        for (int nb = 0; nb < 8; nb++) {
            float p0 = ex2((s[nb][0] - mn0) * LOG2E);
            float p1 = ex2((s[nb][1] - mn0) * LOG2E);
            float p2 = ex2((s[nb][2] - mn1) * LOG2E);
            float p3 = ex2((s[nb][3] - mn1) * LOG2E);
            sum0 += p0 + p1;
            sum1 += p2 + p3;
            int c = nb * 8 + 2 * t;
            *(float2*)&Ps[(m0 + g) * FS + c] = make_float2(to_tf32(p0), to_tf32(p1));
            *(float2*)&Ps[(m0 + g + 8) * FS + c] = make_float2(to_tf32(p2), to_tf32(p3));
        }
        sum0 += __shfl_xor_sync(0xffffffffu, sum0, 1);
        sum0 += __shfl_xor_sync(0xffffffffu, sum0, 2);
        sum1 += __shfl_xor_sync(0xffffffffu, sum1, 1);
        sum1 += __shfl_xor_sync(0xffffffffu, sum1, 2);
        lrow0 = lrow0 * al0 + sum0;
        lrow1 = lrow1 * al1 + sum1;

        #pragma unroll
        for (int nb = 0; nb < 8; nb++) {
            accO[nb][0] *= al0;
            accO[nb][1] *= al0;
            accO[nb][2] *= al1;
            accO[nb][3] *= al1;
        }
        __syncwarp();                                      // P rows warp-private
        // O += P @ V via LDSM
        #pragma unroll
        for (int ks = 0; ks < 8; ks++) {
            const unsigned ko = ks * 32;
            unsigned a0, a1, a2, a3;
            ldsm4(a0, a1, a2, a3, ps_b + aoff + ko);
            #pragma unroll
            for (int nbp = 0; nbp < 4; nbp++) {
                unsigned b0, b1, c0, c1;
                ldsm4(b0, b1, c0, c1, vt_b + boff + (unsigned)(nbp * 16 * FS) * 4 + ko);
                float* O0 = accO[2 * nbp];
                float* O1 = accO[2 * nbp + 1];
                mma8(O0[0], O0[1], O0[2], O0[3], a0, a1, a2, a3, b0, b1);
                mma8(O1[0], O1[1], O1[2], O1[3], a0, a1, a2, a3, c0, c1);
            }
        }
    }

    // epilogue: normalize, split to bf16 hi/lo pairs
    float inv0 = 1.f / lrow0;
    float inv1 = 1.f / lrow1;
    #pragma unroll
    for (int nb = 0; nb < 8; nb++) {
        int cp = h * 32 + nb * 4 + t;
        int r0 = b * NN + i0 + m0 + g;
        int r1 = r0 + 8;
        {
            float o0 = accO[nb][0] * inv0, o1 = accO[nb][1] * inv0;
            unsigned hp = pack_bf16(o1, o0);
            float c0 = __uint_as_float(hp << 16);
            float c1 = __uint_as_float(hp & 0xFFFF0000u);
            unsigned lp = pack_bf16(o1 - c1, o0 - c0);
            g_atth[(size_t)r0 * 256 + cp] = hp;
            g_attl[(size_t)r0 * 256 + cp] = lp;
        }
        {
            float o0 = accO[nb][2] * inv1, o1 = accO[nb][3] * inv1;
            unsigned hp = pack_bf16(o1, o0);
            float c0 = __uint_as_float(hp << 16);
            float c1 = __uint_as_float(hp & 0xFFFF0000u);
            unsigned lp = pack_bf16(o1 - c1, o0 - c0);
            g_atth[(size_t)r1 * 256 + cp] = hp;
            g_attl[(size_t)r1 * 256 + cp] = lp;
        }
    }
}

// =====================================================================
extern "C" void kernel_launch(void* const* d_in, const int* in_sizes, int n_in,
                              void* d_out, int out_size) {
    (void)in_sizes; (void)n_in; (void)out_size;
    const float* x = (const float*)d_in[0];
    const unsigned char* mask = (const unsigned char*)d_in[1];
    const float* bias = (const float*)d_in[2];
    const float* Wq = (const float*)d_in[3];
    const float* Wkv = (const float*)d_in[4];
    const float* Wout = (const float*)d_in[5];
    const float* bout = (const float*)d_in[6];
    float* out = (float*)d_out;

    const int flash_smem = (128 + 64 + 64 + 128) * FS * 4;   // 104448
    cudaFuncSetAttribute(k_flash, cudaFuncAttributeMaxDynamicSharedMemorySize, flash_smem);
    cudaFuncSetAttribute(k_mid, cudaFuncAttributeMaxDynamicSharedMemorySize, GEMM_SMEM);
    cudaFuncSetAttribute(k_gemm_out, cudaFuncAttributeMaxDynamicSharedMemorySize, GEMM_SMEM);

    k_prep<<<1 + NROWS + 2048, 256>>>(mask, x, Wq, Wkv, Wout);
    k_mid<<<19 * 512, 256, GEMM_SMEM>>>(bias);
    k_flash<<<BB * HH * (NN / 128), 256, flash_smem>>>();
    k_gemm_out<<<dim3((DOUT / 64) * (NROWS / 128)), 256, GEMM_SMEM>>>(bout, out);
}